// round 1
// baseline (speedup 1.0000x reference)
#include <cuda_runtime.h>

#define LOG2E 1.4426950408889634f
#define C2OFF (20.0f * LOG2E)

typedef unsigned long long u64;

// ---------------- scratch (static device globals; no allocation) -------------
__device__ float g_th [4][4096][16];   // queries (pre-scaled by log2e)
__device__ float g_key[4][4096][16];   // keys   (phi)
__device__ float g_gv [4][4096][16];   // values (g)
__device__ float g_y  [4][4096][16];   // attention output
__device__ float g_scale[64];
__device__ float g_shift[64];

// ---------------- f32x2 helpers ----------------------------------------------
__device__ __forceinline__ u64 pk2(float lo, float hi) {
    u64 r; asm("mov.b64 %0,{%1,%2};" : "=l"(r) : "f"(lo), "f"(hi)); return r;
}
__device__ __forceinline__ void upk2(u64 v, float &lo, float &hi) {
    asm("mov.b64 {%0,%1},%2;" : "=f"(lo), "=f"(hi) : "l"(v));
}
__device__ __forceinline__ u64 fma2_(u64 a, u64 b, u64 c) {
    u64 d; asm("fma.rn.f32x2 %0,%1,%2,%3;" : "=l"(d) : "l"(a), "l"(b), "l"(c)); return d;
}
__device__ __forceinline__ u64 add2_(u64 a, u64 b) {
    u64 d; asm("add.rn.f32x2 %0,%1,%2;" : "=l"(d) : "l"(a), "l"(b)); return d;
}
__device__ __forceinline__ float ex2f_(float x) {
    float y; asm("ex2.approx.f32 %0,%1;" : "=f"(y) : "f"(x)); return y;
}

// ============================================================================
// K1: downsample (JAX point-sample at (2i+1,2j+1)) + g/theta/phi projections.
// theta is pre-scaled by log2e so softmax runs in exp2 domain.
// grid (16, 4), 256 threads. One thread per downsampled pixel.
// ============================================================================
__global__ __launch_bounds__(256) void k_down_proj(
    const float* __restrict__ x,
    const float* __restrict__ gw, const float* __restrict__ gb,
    const float* __restrict__ tw, const float* __restrict__ tb,
    const float* __restrict__ pw, const float* __restrict__ pb)
{
    __shared__ float sw[48][64];   // [0:16)=g, [16:32)=theta*log2e, [32:48)=phi
    __shared__ float sb[48];
    int tid = threadIdx.x;
    for (int idx = tid; idx < 1024; idx += 256) {
        int o = idx >> 6, c = idx & 63;
        sw[o][c]      = gw[idx];
        sw[16 + o][c] = tw[idx] * LOG2E;
        sw[32 + o][c] = pw[idx];
    }
    if (tid < 16) { sb[tid] = gb[tid]; sb[16 + tid] = tb[tid] * LOG2E; sb[32 + tid] = pb[tid]; }
    __syncthreads();

    int b = blockIdx.y;
    int n = blockIdx.x * 256 + tid;           // 0..4095
    int i = n >> 6, j = n & 63;
    const float* xp = x + (((size_t)b * 64) << 14) + (2 * i + 1) * 128 + (2 * j + 1);

    float acc[48];
#pragma unroll
    for (int o = 0; o < 48; o++) acc[o] = sb[o];

    for (int c = 0; c < 64; c++) {
        float v = xp[(size_t)c << 14];
#pragma unroll
        for (int o = 0; o < 48; o++) acc[o] += sw[o][c] * v;
    }

    float* pg = &g_gv [b][n][0];
    float* pt = &g_th [b][n][0];
    float* pk = &g_key[b][n][0];
#pragma unroll
    for (int o = 0; o < 16; o++) { pg[o] = acc[o]; pt[o] = acc[16 + o]; pk[o] = acc[32 + o]; }
}

// ============================================================================
// K2: attention, N=4096, D=16, max-free softmax (fixed offset 20, exp2 domain).
// grid (32 qtiles, 4 batches), 256 threads.
//   qgroup = tid&31 -> 4 queries (two f32x2 pairs); split = warp id (8 key splits).
// K/V staged in SMEM duplicated (value,value) so LDS.64 feeds FFMA2 directly.
// Split partials merge by pure addition (no max rebasing needed).
// ============================================================================
#define TK 128
__global__ __launch_bounds__(256, 1) void k_attn()
{
    __shared__ u64 skd[TK][16];
    __shared__ u64 svd[TK][16];
    __shared__ u64 mbuf[32][34];   // per qgroup: [0:16)=a0,[16]=lA,[17:33)=a1,[33]=lB

    int tid = threadIdx.x;
    int qg  = tid & 31;
    int sp  = tid >> 5;            // warp id == key split
    int b   = blockIdx.y;
    int qbase = blockIdx.x * 128 + qg * 4;

    const float* thp = &g_th[b][qbase][0];  // 4 queries * 16, contiguous
    u64 q0[16], q1[16];
#pragma unroll
    for (int d = 0; d < 16; d++) {
        q0[d] = pk2(thp[d],      thp[16 + d]);
        q1[d] = pk2(thp[32 + d], thp[48 + d]);
    }

    u64 a0[16], a1[16];
#pragma unroll
    for (int d = 0; d < 16; d++) { a0[d] = 0ULL; a1[d] = 0ULL; }
    u64 lA = 0ULL, lB = 0ULL;
    const u64 negc2 = pk2(-C2OFF, -C2OFF);

    const float* Kp = &g_key[b][0][0];
    const float* Vp = &g_gv [b][0][0];

    for (int t = 0; t < 4096 / TK; t++) {
        __syncthreads();
        for (int idx = tid; idx < TK * 16; idx += 256) {
            int j = idx >> 4, d = idx & 15;
            int key = t * TK + j;
            float kv = Kp[key * 16 + d];
            float vv = Vp[key * 16 + d];
            skd[j][d] = pk2(kv, kv);
            svd[j][d] = pk2(vv, vv);
        }
        __syncthreads();

        for (int ii = 0; ii < TK / 8; ii++) {
            int j = ii * 8 + sp;
            u64 s0 = negc2, s1 = negc2;
#pragma unroll
            for (int d = 0; d < 16; d++) {
                u64 kk = skd[j][d];
                s0 = fma2_(q0[d], kk, s0);
                s1 = fma2_(q1[d], kk, s1);
            }
            float e00, e01, e10, e11;
            upk2(s0, e00, e01); upk2(s1, e10, e11);
            u64 p0 = pk2(ex2f_(e00), ex2f_(e01));
            u64 p1 = pk2(ex2f_(e10), ex2f_(e11));
            lA = add2_(lA, p0);
            lB = add2_(lB, p1);
#pragma unroll
            for (int d = 0; d < 16; d++) {
                u64 vv = svd[j][d];
                a0[d] = fma2_(p0, vv, a0[d]);
                a1[d] = fma2_(p1, vv, a1[d]);
            }
        }
    }

    // ---- merge 8 key-splits (pure sums; sequential by split, deterministic) ----
    for (int s = 0; s < 8; s++) {
        if (sp == s) {
            if (s == 0) {
#pragma unroll
                for (int d = 0; d < 16; d++) { mbuf[qg][d] = a0[d]; mbuf[qg][17 + d] = a1[d]; }
                mbuf[qg][16] = lA; mbuf[qg][33] = lB;
            } else {
#pragma unroll
                for (int d = 0; d < 16; d++) {
                    mbuf[qg][d]      = add2_(mbuf[qg][d],      a0[d]);
                    mbuf[qg][17 + d] = add2_(mbuf[qg][17 + d], a1[d]);
                }
                mbuf[qg][16] = add2_(mbuf[qg][16], lA);
                mbuf[qg][33] = add2_(mbuf[qg][33], lB);
            }
        }
        __syncthreads();
    }

    // ---- normalize + write y: 32 qg * 2 pairs * 16 d = 1024 packed outputs ----
    for (int it = tid; it < 1024; it += 256) {
        int qg2 = it >> 5;
        int rem = it & 31;
        int pr  = rem >> 4;
        int d   = rem & 15;
        u64 av = mbuf[qg2][pr * 17 + d];
        u64 lv = mbuf[qg2][pr * 17 + 16];
        float ax, ay, lx, ly;
        upk2(av, ax, ay); upk2(lv, lx, ly);
        int q0i = blockIdx.x * 128 + qg2 * 4 + pr * 2;
        g_y[b][q0i][d]     = __fdividef(ax, lx);
        g_y[b][q0i + 1][d] = __fdividef(ay, ly);
    }
}

// ============================================================================
// K3: upsample 2x (JAX: out[i] = 0.5*(y[max((i-1)>>1,0)] + y[i>>1]) per axis)
//     + out projection (16->64) + residual. Writes z into d_out.
// grid (64, 4), 256 threads; one thread per full-res pixel.
// ============================================================================
__global__ __launch_bounds__(256) void k_up_out(
    const float* __restrict__ x,
    const float* __restrict__ ow, const float* __restrict__ ob,
    float* __restrict__ zout)
{
    __shared__ float sow[64][16];
    __shared__ float sob[64];
    int tid = threadIdx.x;
    for (int idx = tid; idx < 1024; idx += 256) sow[idx >> 4][idx & 15] = ow[idx];
    if (tid < 64) sob[tid] = ob[tid];
    __syncthreads();

    int b = blockIdx.y;
    int pix = blockIdx.x * 256 + tid;   // 0..16383
    int i = pix >> 7, j = pix & 127;

    int r0 = (i - 1) >> 1; if (r0 < 0) r0 = 0;
    int r1 = i >> 1;
    int c0 = (j - 1) >> 1; if (c0 < 0) c0 = 0;
    int c1 = j >> 1;

    const float* yb = &g_y[b][0][0];
    const float* t00 = yb + (r0 * 64 + c0) * 16;
    const float* t01 = yb + (r0 * 64 + c1) * 16;
    const float* t10 = yb + (r1 * 64 + c0) * 16;
    const float* t11 = yb + (r1 * 64 + c1) * 16;

    float yup[16];
#pragma unroll
    for (int d = 0; d < 16; d++)
        yup[d] = 0.25f * (t00[d] + t01[d] + t10[d] + t11[d]);

#pragma unroll 4
    for (int c = 0; c < 64; c++) {
        float s = sob[c];
#pragma unroll
        for (int d = 0; d < 16; d++) s += sow[c][d] * yup[d];
        size_t o = (((size_t)(b * 64 + c)) << 14) + pix;
        zout[o] = x[o] + s;
    }
}

// ============================================================================
// K4a: per-channel batch stats over (B,H,W), deterministic tree reduction.
// grid 64 (one block per channel), 256 threads.
// ============================================================================
__global__ __launch_bounds__(256) void k_bnstats(
    const float* __restrict__ z,
    const float* __restrict__ gamma, const float* __restrict__ beta)
{
    __shared__ float ss[256], ss2[256];
    int c = blockIdx.x, tid = threadIdx.x;
    float s = 0.f, s2 = 0.f;
    for (int b = 0; b < 4; b++) {
        const float* p = z + (((size_t)(b * 64 + c)) << 14);
        for (int idx = tid; idx < 16384; idx += 256) {
            float v = p[idx];
            s += v; s2 += v * v;
        }
    }
    ss[tid] = s; ss2[tid] = s2;
    __syncthreads();
    for (int off = 128; off; off >>= 1) {
        if (tid < off) { ss[tid] += ss[tid + off]; ss2[tid] += ss2[tid + off]; }
        __syncthreads();
    }
    if (tid == 0) {
        const float inv = 1.0f / 65536.0f;
        float mean = ss[0] * inv;
        float var  = ss2[0] * inv - mean * mean;
        float sc = gamma[c] * rsqrtf(var + 1e-5f);
        g_scale[c] = sc;
        g_shift[c] = beta[c] - mean * sc;
    }
}

// K4b: in-place normalize, vectorized float4. grid 4096, 256 threads.
__global__ __launch_bounds__(256) void k_bnapply(float4* __restrict__ z)
{
    int idx = blockIdx.x * 256 + threadIdx.x;  // 0..1048575
    int c = (idx >> 12) & 63;                   // 4096 float4 per (b,c) plane
    float sc = g_scale[c], sh = g_shift[c];
    float4 v = z[idx];
    v.x = v.x * sc + sh; v.y = v.y * sc + sh;
    v.z = v.z * sc + sh; v.w = v.w * sc + sh;
    z[idx] = v;
}

// ============================================================================
extern "C" void kernel_launch(void* const* d_in, const int* in_sizes, int n_in,
                              void* d_out, int out_size)
{
    const float* x   = (const float*)d_in[0];
    const float* gw  = (const float*)d_in[1];
    const float* gb  = (const float*)d_in[2];
    const float* tw  = (const float*)d_in[3];
    const float* tb  = (const float*)d_in[4];
    const float* pw  = (const float*)d_in[5];
    const float* pb  = (const float*)d_in[6];
    const float* ow  = (const float*)d_in[7];
    const float* ob  = (const float*)d_in[8];
    const float* gam = (const float*)d_in[9];
    const float* bet = (const float*)d_in[10];
    float* out = (float*)d_out;

    k_down_proj<<<dim3(16, 4), 256>>>(x, gw, gb, tw, tb, pw, pb);
    k_attn     <<<dim3(32, 4), 256>>>();
    k_up_out   <<<dim3(64, 4), 256>>>(x, ow, ob, out);
    k_bnstats  <<<64, 256>>>(out, gam, bet);
    k_bnapply  <<<4096, 256>>>((float4*)out);
}

// round 2
// speedup vs baseline: 1.0911x; 1.0911x over previous
#include <cuda_runtime.h>

#define LOG2E 1.4426950408889634f
#define C2OFF (20.0f * LOG2E)

typedef unsigned long long u64;

// ---------------- scratch (static device globals; no allocation) -------------
__device__ float g_th  [4][4096][16];   // queries (pre-scaled by log2e)
__device__ u64   g_keyd[4][4096][16];   // keys, duplicated (k,k) f32x2
__device__ u64   g_gvd [4][4096][16];   // values, duplicated (v,v) f32x2
__device__ float g_y   [4][4096][16];   // attention output
__device__ float g_sum [64];
__device__ float g_sum2[64];

// ---------------- helpers ----------------------------------------------------
__device__ __forceinline__ u64 pk2(float lo, float hi) {
    u64 r; asm("mov.b64 %0,{%1,%2};" : "=l"(r) : "f"(lo), "f"(hi)); return r;
}
__device__ __forceinline__ void upk2(u64 v, float &lo, float &hi) {
    asm("mov.b64 {%0,%1},%2;" : "=f"(lo), "=f"(hi) : "l"(v));
}
__device__ __forceinline__ u64 fma2_(u64 a, u64 b, u64 c) {
    u64 d; asm("fma.rn.f32x2 %0,%1,%2,%3;" : "=l"(d) : "l"(a), "l"(b), "l"(c)); return d;
}
__device__ __forceinline__ u64 add2_(u64 a, u64 b) {
    u64 d; asm("add.rn.f32x2 %0,%1,%2;" : "=l"(d) : "l"(a), "l"(b)); return d;
}
__device__ __forceinline__ float ex2f_(float x) {
    float y; asm("ex2.approx.f32 %0,%1;" : "=f"(y) : "f"(x)); return y;
}
__device__ __forceinline__ void lds128(u64 &a, u64 &b, unsigned addr) {
    asm("ld.shared.v2.u64 {%0,%1},[%2];" : "=l"(a), "=l"(b) : "r"(addr));
}
__device__ __forceinline__ void cpa16(unsigned saddr, const void* g) {
    asm volatile("{.reg .u64 gp; cvta.to.global.u64 gp, %1;"
                 " cp.async.cg.shared.global [%0],[gp],16;}"
                 :: "r"(saddr), "l"(g));
}
__device__ __forceinline__ void cpa_commit() {
    asm volatile("cp.async.commit_group;");
}

// ============================================================================
// K1: downsample (point-sample at (2i+1,2j+1)) + g/theta/phi projections.
// Writes q as float, K/V pre-duplicated as f32x2. Also zeroes BN accumulators.
// ============================================================================
__global__ __launch_bounds__(256) void k_down_proj(
    const float* __restrict__ x,
    const float* __restrict__ gw, const float* __restrict__ gb,
    const float* __restrict__ tw, const float* __restrict__ tb,
    const float* __restrict__ pw, const float* __restrict__ pb)
{
    __shared__ float sw[48][64];   // [0:16)=g, [16:32)=theta*log2e, [32:48)=phi
    __shared__ float sb[48];
    int tid = threadIdx.x;
    if (blockIdx.x == 0 && blockIdx.y == 0 && tid < 128) {
        if (tid < 64) g_sum[tid] = 0.f; else g_sum2[tid - 64] = 0.f;
    }
    for (int idx = tid; idx < 1024; idx += 256) {
        int o = idx >> 6, c = idx & 63;
        sw[o][c]      = gw[idx];
        sw[16 + o][c] = tw[idx] * LOG2E;
        sw[32 + o][c] = pw[idx];
    }
    if (tid < 16) { sb[tid] = gb[tid]; sb[16 + tid] = tb[tid] * LOG2E; sb[32 + tid] = pb[tid]; }
    __syncthreads();

    int b = blockIdx.y;
    int n = blockIdx.x * 256 + tid;           // 0..4095
    int i = n >> 6, j = n & 63;
    const float* xp = x + (((size_t)b * 64) << 14) + (2 * i + 1) * 128 + (2 * j + 1);

    float acc[48];
#pragma unroll
    for (int o = 0; o < 48; o++) acc[o] = sb[o];

    for (int c = 0; c < 64; c++) {
        float v = xp[(size_t)c << 14];
#pragma unroll
        for (int o = 0; o < 48; o++) acc[o] += sw[o][c] * v;
    }

    float* pt = &g_th[b][n][0];
#pragma unroll
    for (int o = 0; o < 16; o++) {
        g_gvd [b][n][o] = pk2(acc[o], acc[o]);
        pt[o]           = acc[16 + o];
        g_keyd[b][n][o] = pk2(acc[32 + o], acc[32 + o]);
    }
}

// ============================================================================
// K2: attention, N=4096, D=16, max-free softmax (fixed offset 20, exp2 domain).
// grid (32 qtiles, 4 batches), 256 threads (8 warps).
//   qgroup = tid&31 -> 4 queries (two f32x2 pairs); warp id = key split (8).
// K/V tiles cp.async double-buffered; LDS.128 feeds FFMA2 directly.
// ============================================================================
#define TK 128
#define NT 32
extern __shared__ u64 dynsm[];   // 65536B: K[2][2048] | V[2][2048]

__global__ __launch_bounds__(256, 1) void k_attn()
{
    int tid = threadIdx.x;
    int qg  = tid & 31;
    int sp  = tid >> 5;            // warp id == key split
    int b   = blockIdx.y;
    int qbase = blockIdx.x * 128 + qg * 4;

    unsigned sbase = (unsigned)__cvta_generic_to_shared(dynsm);
    // layout: K buf0 [0,16K) K buf1 [16K,32K) V buf0 [32K,48K) V buf1 [48K,64K)

    const float* thp = &g_th[b][qbase][0];
    u64 q0[16], q1[16];
#pragma unroll
    for (int d = 0; d < 16; d++) {
        q0[d] = pk2(thp[d],      thp[16 + d]);
        q1[d] = pk2(thp[32 + d], thp[48 + d]);
    }

    u64 a0[16], a1[16];
#pragma unroll
    for (int d = 0; d < 16; d++) { a0[d] = 0ULL; a1[d] = 0ULL; }
    u64 lA = 0ULL, lB = 0ULL;
    const u64 negc2 = pk2(-C2OFF, -C2OFF);

    const u64* Kg = &g_keyd[b][0][0];
    const u64* Vg = &g_gvd [b][0][0];

    // prefetch tile 0 into buf 0
    {
        const u64* ks = Kg;                  // 2048 u64
        const u64* vs = Vg;
#pragma unroll
        for (int k = 0; k < 4; k++) {
            int ch = tid + k * 256;          // 16B chunk index, 1024 per array
            cpa16(sbase + ch * 16,         ks + ch * 2);
            cpa16(sbase + 32768 + ch * 16, vs + ch * 2);
        }
        cpa_commit();
    }

    for (int t = 0; t < NT; t++) {
        int buf = t & 1;
        if (t + 1 < NT) {
            int nb = (t + 1) & 1;
            const u64* ks = Kg + (t + 1) * TK * 16;
            const u64* vs = Vg + (t + 1) * TK * 16;
#pragma unroll
            for (int k = 0; k < 4; k++) {
                int ch = tid + k * 256;
                cpa16(sbase + nb * 16384 + ch * 16,         ks + ch * 2);
                cpa16(sbase + 32768 + nb * 16384 + ch * 16, vs + ch * 2);
            }
            cpa_commit();
            asm volatile("cp.async.wait_group 1;");
        } else {
            asm volatile("cp.async.wait_group 0;");
        }
        __syncthreads();

        unsigned skb = sbase + buf * 16384;
        unsigned svb = sbase + 32768 + buf * 16384;

#pragma unroll 1
        for (int ii = 0; ii < TK / 8; ii++) {
            int j = ii * 8 + sp;
            unsigned ka = skb + j * 128;
            u64 s0a = negc2, s0b = 0ULL, s1a = negc2, s1b = 0ULL;
#pragma unroll
            for (int dd = 0; dd < 16; dd += 2) {
                u64 k0, k1; lds128(k0, k1, ka + dd * 8);
                s0a = fma2_(q0[dd],     k0, s0a);
                s1a = fma2_(q1[dd],     k0, s1a);
                s0b = fma2_(q0[dd + 1], k1, s0b);
                s1b = fma2_(q1[dd + 1], k1, s1b);
            }
            u64 s0 = add2_(s0a, s0b);
            u64 s1 = add2_(s1a, s1b);
            float e00, e01, e10, e11;
            upk2(s0, e00, e01); upk2(s1, e10, e11);
            u64 p0 = pk2(ex2f_(e00), ex2f_(e01));
            u64 p1 = pk2(ex2f_(e10), ex2f_(e11));
            lA = add2_(lA, p0);
            lB = add2_(lB, p1);
            unsigned va = svb + j * 128;
#pragma unroll
            for (int dd = 0; dd < 16; dd += 2) {
                u64 v0, v1; lds128(v0, v1, va + dd * 8);
                a0[dd]     = fma2_(p0, v0, a0[dd]);
                a1[dd]     = fma2_(p1, v0, a1[dd]);
                a0[dd + 1] = fma2_(p0, v1, a0[dd + 1]);
                a1[dd + 1] = fma2_(p1, v1, a1[dd + 1]);
            }
        }
        __syncthreads();
    }

    // ---- merge 8 key-splits (aliases tile smem; all tiles done) -------------
    u64 (*mbuf)[34] = (u64 (*)[34])dynsm;   // 32*34*8 = 8704B
    for (int s = 0; s < 8; s++) {
        if (sp == s) {
            if (s == 0) {
#pragma unroll
                for (int d = 0; d < 16; d++) { mbuf[qg][d] = a0[d]; mbuf[qg][17 + d] = a1[d]; }
                mbuf[qg][16] = lA; mbuf[qg][33] = lB;
            } else {
#pragma unroll
                for (int d = 0; d < 16; d++) {
                    mbuf[qg][d]      = add2_(mbuf[qg][d],      a0[d]);
                    mbuf[qg][17 + d] = add2_(mbuf[qg][17 + d], a1[d]);
                }
                mbuf[qg][16] = add2_(mbuf[qg][16], lA);
                mbuf[qg][33] = add2_(mbuf[qg][33], lB);
            }
        }
        __syncthreads();
    }

    // ---- normalize + write y ------------------------------------------------
    for (int it = tid; it < 1024; it += 256) {
        int qg2 = it >> 5;
        int rem = it & 31;
        int pr  = rem >> 4;
        int d   = rem & 15;
        u64 av = mbuf[qg2][pr * 17 + d];
        u64 lv = mbuf[qg2][pr * 17 + 16];
        float ax, ay, lx, ly;
        upk2(av, ax, ay); upk2(lv, lx, ly);
        int q0i = blockIdx.x * 128 + qg2 * 4 + pr * 2;
        g_y[b][q0i][d]     = __fdividef(ax, lx);
        g_y[b][q0i + 1][d] = __fdividef(ay, ly);
    }
}

// ============================================================================
// K3: upsample 2x + out projection (16->64) + residual. Writes z into d_out.
// ============================================================================
__global__ __launch_bounds__(256) void k_up_out(
    const float* __restrict__ x,
    const float* __restrict__ ow, const float* __restrict__ ob,
    float* __restrict__ zout)
{
    __shared__ float sow[64][16];
    __shared__ float sob[64];
    int tid = threadIdx.x;
    for (int idx = tid; idx < 1024; idx += 256) sow[idx >> 4][idx & 15] = ow[idx];
    if (tid < 64) sob[tid] = ob[tid];
    __syncthreads();

    int b = blockIdx.y;
    int pix = blockIdx.x * 256 + tid;   // 0..16383
    int i = pix >> 7, j = pix & 127;

    int r0 = (i - 1) >> 1; if (r0 < 0) r0 = 0;
    int r1 = i >> 1;
    int c0 = (j - 1) >> 1; if (c0 < 0) c0 = 0;
    int c1 = j >> 1;

    const float* yb = &g_y[b][0][0];
    const float4* t00 = (const float4*)(yb + (r0 * 64 + c0) * 16);
    const float4* t01 = (const float4*)(yb + (r0 * 64 + c1) * 16);
    const float4* t10 = (const float4*)(yb + (r1 * 64 + c0) * 16);
    const float4* t11 = (const float4*)(yb + (r1 * 64 + c1) * 16);

    float yup[16];
#pragma unroll
    for (int r = 0; r < 4; r++) {
        float4 a = t00[r], bb = t01[r], c = t10[r], d = t11[r];
        yup[r * 4 + 0] = 0.25f * (a.x + bb.x + c.x + d.x);
        yup[r * 4 + 1] = 0.25f * (a.y + bb.y + c.y + d.y);
        yup[r * 4 + 2] = 0.25f * (a.z + bb.z + c.z + d.z);
        yup[r * 4 + 3] = 0.25f * (a.w + bb.w + c.w + d.w);
    }

#pragma unroll 4
    for (int c = 0; c < 64; c++) {
        float s = sob[c];
#pragma unroll
        for (int d = 0; d < 16; d++) s += sow[c][d] * yup[d];
        size_t o = (((size_t)(b * 64 + c)) << 14) + pix;
        zout[o] = x[o] + s;
    }
}

// ============================================================================
// K4a: partial BN stats, 512 blocks (8 slices x 64 channels), atomic merge.
// ============================================================================
__global__ __launch_bounds__(256) void k_bnpart(const float* __restrict__ z)
{
    __shared__ float ss[256], ss2[256];
    int c = blockIdx.x >> 3, s = blockIdx.x & 7;
    int tid = threadIdx.x;
    float sum = 0.f, sum2 = 0.f;
#pragma unroll
    for (int b = 0; b < 4; b++) {
        const float4* p = (const float4*)(z + (((size_t)(b * 64 + c)) << 14)) + s * 512;
#pragma unroll
        for (int k = 0; k < 2; k++) {
            float4 v = p[tid + k * 256];
            sum  += v.x + v.y + v.z + v.w;
            sum2 += v.x * v.x + v.y * v.y + v.z * v.z + v.w * v.w;
        }
    }
    ss[tid] = sum; ss2[tid] = sum2;
    __syncthreads();
    for (int off = 128; off; off >>= 1) {
        if (tid < off) { ss[tid] += ss[tid + off]; ss2[tid] += ss2[tid + off]; }
        __syncthreads();
    }
    if (tid == 0) {
        atomicAdd(&g_sum[c],  ss[0]);
        atomicAdd(&g_sum2[c], ss2[0]);
    }
}

// K4b: normalize in place; scale/shift derived from accumulated sums per block.
__global__ __launch_bounds__(256) void k_bnapply(
    float4* __restrict__ z,
    const float* __restrict__ gamma, const float* __restrict__ beta)
{
    int blk = blockIdx.x;               // 1024 blocks, quarter-plane each
    int c = (blk >> 2) & 63;
    const float inv = 1.0f / 65536.0f;
    float mean = g_sum[c] * inv;
    float var  = g_sum2[c] * inv - mean * mean;
    float sc = gamma[c] * rsqrtf(var + 1e-5f);
    float sh = beta[c] - mean * sc;
    int base = blk * 1024 + threadIdx.x;
#pragma unroll
    for (int k = 0; k < 4; k++) {
        float4 v = z[base + k * 256];
        v.x = v.x * sc + sh; v.y = v.y * sc + sh;
        v.z = v.z * sc + sh; v.w = v.w * sc + sh;
        z[base + k * 256] = v;
    }
}

// ============================================================================
extern "C" void kernel_launch(void* const* d_in, const int* in_sizes, int n_in,
                              void* d_out, int out_size)
{
    const float* x   = (const float*)d_in[0];
    const float* gw  = (const float*)d_in[1];
    const float* gb  = (const float*)d_in[2];
    const float* tw  = (const float*)d_in[3];
    const float* tb  = (const float*)d_in[4];
    const float* pw  = (const float*)d_in[5];
    const float* pb  = (const float*)d_in[6];
    const float* ow  = (const float*)d_in[7];
    const float* ob  = (const float*)d_in[8];
    const float* gam = (const float*)d_in[9];
    const float* bet = (const float*)d_in[10];
    float* out = (float*)d_out;

    cudaFuncSetAttribute(k_attn, cudaFuncAttributeMaxDynamicSharedMemorySize, 65536);

    k_down_proj<<<dim3(16, 4), 256>>>(x, gw, gb, tw, tb, pw, pb);
    k_attn     <<<dim3(32, 4), 256, 65536>>>();
    k_up_out   <<<dim3(64, 4), 256>>>(x, ow, ob, out);
    k_bnpart   <<<512, 256>>>(out);
    k_bnapply  <<<1024, 256>>>((float4*)out, gam, bet);
}

// round 3
// speedup vs baseline: 1.1760x; 1.0778x over previous
#include <cuda_runtime.h>

#define LOG2E 1.4426950408889634f
#define C2OFF (20.0f * LOG2E)

typedef unsigned long long u64;

// ---------------- scratch (static device globals; no allocation) -------------
__device__ float g_th  [4][4096][16];        // queries (pre-scaled by log2e)
__device__ float g_keyT[4][32][16][128];     // keys, transposed per 128-key tile
__device__ float g_v   [4][4096][16];        // values, natural layout
__device__ float g_y   [4][4096][16];        // attention output
__device__ float g_sum [64];
__device__ float g_sum2[64];

// ---------------- helpers ----------------------------------------------------
__device__ __forceinline__ u64 pk2(float lo, float hi) {
    u64 r; asm("mov.b64 %0,{%1,%2};" : "=l"(r) : "f"(lo), "f"(hi)); return r;
}
__device__ __forceinline__ void upk2(u64 v, float &lo, float &hi) {
    asm("mov.b64 {%0,%1},%2;" : "=f"(lo), "=f"(hi) : "l"(v));
}
__device__ __forceinline__ u64 fma2_(u64 a, u64 b, u64 c) {
    u64 d; asm("fma.rn.f32x2 %0,%1,%2,%3;" : "=l"(d) : "l"(a), "l"(b), "l"(c)); return d;
}
__device__ __forceinline__ u64 add2_(u64 a, u64 b) {
    u64 d; asm("add.rn.f32x2 %0,%1,%2;" : "=l"(d) : "l"(a), "l"(b)); return d;
}
__device__ __forceinline__ float ex2f_(float x) {
    float y; asm("ex2.approx.f32 %0,%1;" : "=f"(y) : "f"(x)); return y;
}
__device__ __forceinline__ void lds128(u64 &a, u64 &b, unsigned addr) {
    asm("ld.shared.v2.u64 {%0,%1},[%2];" : "=l"(a), "=l"(b) : "r"(addr));
}
__device__ __forceinline__ void cpa16(unsigned saddr, const void* g) {
    asm volatile("{.reg .u64 gp; cvta.to.global.u64 gp, %1;"
                 " cp.async.cg.shared.global [%0],[gp],16;}"
                 :: "r"(saddr), "l"(g));
}
__device__ __forceinline__ void cpa_commit() {
    asm volatile("cp.async.commit_group;");
}

// ============================================================================
// K1: downsample (point-sample at (2i+1,2j+1)) + g/theta/phi projections.
// K written TRANSPOSED per 128-key tile; V natural. Zeroes BN accumulators.
// ============================================================================
__global__ __launch_bounds__(256) void k_down_proj(
    const float* __restrict__ x,
    const float* __restrict__ gw, const float* __restrict__ gb,
    const float* __restrict__ tw, const float* __restrict__ tb,
    const float* __restrict__ pw, const float* __restrict__ pb)
{
    __shared__ float sw[48][64];   // [0:16)=g, [16:32)=theta*log2e, [32:48)=phi
    __shared__ float sb[48];
    int tid = threadIdx.x;
    if (blockIdx.x == 0 && blockIdx.y == 0 && tid < 128) {
        if (tid < 64) g_sum[tid] = 0.f; else g_sum2[tid - 64] = 0.f;
    }
    for (int idx = tid; idx < 1024; idx += 256) {
        int o = idx >> 6, c = idx & 63;
        sw[o][c]      = gw[idx];
        sw[16 + o][c] = tw[idx] * LOG2E;
        sw[32 + o][c] = pw[idx];
    }
    if (tid < 16) { sb[tid] = gb[tid]; sb[16 + tid] = tb[tid] * LOG2E; sb[32 + tid] = pb[tid]; }
    __syncthreads();

    int b = blockIdx.y;
    int n = blockIdx.x * 256 + tid;           // 0..4095
    int i = n >> 6, j = n & 63;
    const float* xp = x + (((size_t)b * 64) << 14) + (2 * i + 1) * 128 + (2 * j + 1);

    float acc[48];
#pragma unroll
    for (int o = 0; o < 48; o++) acc[o] = sb[o];

    for (int c = 0; c < 64; c++) {
        float v = xp[(size_t)c << 14];
#pragma unroll
        for (int o = 0; o < 48; o++) acc[o] += sw[o][c] * v;
    }

    float* pt = &g_th[b][n][0];
    float* pv = &g_v [b][n][0];
    int tile = n >> 7, jj = n & 127;
#pragma unroll
    for (int o = 0; o < 16; o++) {
        pv[o] = acc[o];
        pt[o] = acc[16 + o];
        g_keyT[b][tile][o][jj] = acc[32 + o];   // coalesced per fixed o
    }
}

// ============================================================================
// K2: attention, N=4096, D=16, max-free softmax (fixed offset 20, exp2 domain).
// grid (64 qtiles, 4 batches) = 256 CTAs, 256 threads, 32KB smem -> 2 CTAs/SM.
//   qg = tid&31 -> 2 queries; warp id = key split (8 splits of 512 keys).
// Keys packed in f32x2 lanes for QK^T (K transposed in smem); d-pairs packed
// for PV (V natural). All smem bytes unique: 8 LDS.128 per key per thread.
// ============================================================================
#define TK 128
#define NT 32
extern __shared__ u64 dynsm[];   // 32768B: K0 |8K| K1 |8K| V0 |8K| V1 |8K|

__global__ __launch_bounds__(256, 2) void k_attn()
{
    int tid = threadIdx.x;
    int qg  = tid & 31;
    int sp  = tid >> 5;            // warp id == key split
    int b   = blockIdx.y;
    int qbase = blockIdx.x * 64;

    unsigned sbase = (unsigned)__cvta_generic_to_shared(dynsm);

    // load 2 queries (32 floats) via float4
    const float4* thp = (const float4*)&g_th[b][qbase + 2 * qg][0];
    float q0[16], q1[16];
#pragma unroll
    for (int r = 0; r < 4; r++) {
        float4 v0 = thp[r], v1 = thp[4 + r];
        q0[r * 4 + 0] = v0.x; q0[r * 4 + 1] = v0.y; q0[r * 4 + 2] = v0.z; q0[r * 4 + 3] = v0.w;
        q1[r * 4 + 0] = v1.x; q1[r * 4 + 1] = v1.y; q1[r * 4 + 2] = v1.z; q1[r * 4 + 3] = v1.w;
    }

    u64 a0[8], a1[8];
#pragma unroll
    for (int d = 0; d < 8; d++) { a0[d] = 0ULL; a1[d] = 0ULL; }
    float la = 0.f, lb = 0.f;
    const u64 negc2 = pk2(-C2OFF, -C2OFF);

    const float* Kg = &g_keyT[b][0][0][0];   // 32 tiles * 2048 floats
    const float* Vg = &g_v   [b][0][0];

    // prefetch tile 0
#pragma unroll
    for (int k = 0; k < 2; k++) {
        int ch = tid + k * 256;              // 512 chunks of 16B per array
        cpa16(sbase + ch * 16,         Kg + ch * 4);
        cpa16(sbase + 16384 + ch * 16, Vg + ch * 4);
    }
    cpa_commit();

    for (int t = 0; t < NT; t++) {
        if (t + 1 < NT) {
            int nb = (t + 1) & 1;
            const float* ks = Kg + (t + 1) * 2048;
            const float* vs = Vg + (t + 1) * 2048;
#pragma unroll
            for (int k = 0; k < 2; k++) {
                int ch = tid + k * 256;
                cpa16(sbase + nb * 8192 + ch * 16,         ks + ch * 4);
                cpa16(sbase + 16384 + nb * 8192 + ch * 16, vs + ch * 4);
            }
            cpa_commit();
            asm volatile("cp.async.wait_group 1;");
        } else {
            asm volatile("cp.async.wait_group 0;");
        }
        __syncthreads();

        unsigned skb = sbase + (t & 1) * 8192;           // K: [d][j] floats
        unsigned svb = sbase + 16384 + (t & 1) * 8192;   // V: [j][d] floats

#pragma unroll 1
        for (int ii = 0; ii < 4; ii++) {
            int j0 = ii * 32 + sp * 4;       // this thread's 4 keys
            unsigned ka = skb + j0 * 4;
            u64 sA0 = negc2, sA1 = negc2, sB0 = negc2, sB1 = negc2;
#pragma unroll
            for (int d = 0; d < 16; d++) {
                u64 k01, k23; lds128(k01, k23, ka + d * 512);
                u64 qa = pk2(q0[d], q0[d]);
                u64 qb = pk2(q1[d], q1[d]);
                sA0 = fma2_(qa, k01, sA0); sA1 = fma2_(qa, k23, sA1);
                sB0 = fma2_(qb, k01, sB0); sB1 = fma2_(qb, k23, sB1);
            }
            float pa[4], pb[4], e0, e1;
            upk2(sA0, e0, e1); pa[0] = ex2f_(e0); pa[1] = ex2f_(e1);
            upk2(sA1, e0, e1); pa[2] = ex2f_(e0); pa[3] = ex2f_(e1);
            upk2(sB0, e0, e1); pb[0] = ex2f_(e0); pb[1] = ex2f_(e1);
            upk2(sB1, e0, e1); pb[2] = ex2f_(e0); pb[3] = ex2f_(e1);
            la += (pa[0] + pa[1]) + (pa[2] + pa[3]);
            lb += (pb[0] + pb[1]) + (pb[2] + pb[3]);
#pragma unroll
            for (int jj = 0; jj < 4; jj++) {
                u64 pda = pk2(pa[jj], pa[jj]);
                u64 pdb = pk2(pb[jj], pb[jj]);
                unsigned va = svb + (j0 + jj) * 64;
#pragma unroll
                for (int dpp = 0; dpp < 4; dpp++) {
                    u64 v01, v23; lds128(v01, v23, va + dpp * 16);
                    a0[2 * dpp]     = fma2_(pda, v01, a0[2 * dpp]);
                    a0[2 * dpp + 1] = fma2_(pda, v23, a0[2 * dpp + 1]);
                    a1[2 * dpp]     = fma2_(pdb, v01, a1[2 * dpp]);
                    a1[2 * dpp + 1] = fma2_(pdb, v23, a1[2 * dpp + 1]);
                }
            }
        }
        __syncthreads();
    }

    // ---- merge 8 key-splits (aliases tile smem; deterministic order) --------
    u64 (*marr)[2][8] = (u64 (*)[2][8])dynsm;          // 4096B
    float* larr = (float*)(dynsm + 512);               // 256B
    for (int s = 0; s < 8; s++) {
        if (sp == s) {
            if (s == 0) {
#pragma unroll
                for (int d = 0; d < 8; d++) { marr[qg][0][d] = a0[d]; marr[qg][1][d] = a1[d]; }
                larr[qg * 2] = la; larr[qg * 2 + 1] = lb;
            } else {
#pragma unroll
                for (int d = 0; d < 8; d++) {
                    marr[qg][0][d] = add2_(marr[qg][0][d], a0[d]);
                    marr[qg][1][d] = add2_(marr[qg][1][d], a1[d]);
                }
                larr[qg * 2]     += la;
                larr[qg * 2 + 1] += lb;
            }
        }
        __syncthreads();
    }

    // ---- normalize + write y: 32 qg * 2 q * 8 dpairs = 512 pairs ------------
    for (int it = tid; it < 512; it += 256) {
        int qg2 = it >> 4, q = (it >> 3) & 1, dp = it & 7;
        u64 av = marr[qg2][q][dp];
        float l = larr[qg2 * 2 + q];
        float ax, ay; upk2(av, ax, ay);
        float inv = __fdividef(1.f, l);
        int qi = qbase + qg2 * 2 + q;
        g_y[b][qi][2 * dp]     = ax * inv;
        g_y[b][qi][2 * dp + 1] = ay * inv;
    }
}

// ============================================================================
// K3: upsample 2x + out projection (16->64) + residual. Writes z into d_out.
// ============================================================================
__global__ __launch_bounds__(256) void k_up_out(
    const float* __restrict__ x,
    const float* __restrict__ ow, const float* __restrict__ ob,
    float* __restrict__ zout)
{
    __shared__ float sow[64][16];
    __shared__ float sob[64];
    int tid = threadIdx.x;
    for (int idx = tid; idx < 1024; idx += 256) sow[idx >> 4][idx & 15] = ow[idx];
    if (tid < 64) sob[tid] = ob[tid];
    __syncthreads();

    int b = blockIdx.y;
    int pix = blockIdx.x * 256 + tid;   // 0..16383
    int i = pix >> 7, j = pix & 127;

    int r0 = (i - 1) >> 1; if (r0 < 0) r0 = 0;
    int r1 = i >> 1;
    int c0 = (j - 1) >> 1; if (c0 < 0) c0 = 0;
    int c1 = j >> 1;

    const float* yb = &g_y[b][0][0];
    const float4* t00 = (const float4*)(yb + (r0 * 64 + c0) * 16);
    const float4* t01 = (const float4*)(yb + (r0 * 64 + c1) * 16);
    const float4* t10 = (const float4*)(yb + (r1 * 64 + c0) * 16);
    const float4* t11 = (const float4*)(yb + (r1 * 64 + c1) * 16);

    float yup[16];
#pragma unroll
    for (int r = 0; r < 4; r++) {
        float4 a = t00[r], bb = t01[r], c = t10[r], d = t11[r];
        yup[r * 4 + 0] = 0.25f * (a.x + bb.x + c.x + d.x);
        yup[r * 4 + 1] = 0.25f * (a.y + bb.y + c.y + d.y);
        yup[r * 4 + 2] = 0.25f * (a.z + bb.z + c.z + d.z);
        yup[r * 4 + 3] = 0.25f * (a.w + bb.w + c.w + d.w);
    }

#pragma unroll 4
    for (int c = 0; c < 64; c++) {
        float s = sob[c];
#pragma unroll
        for (int d = 0; d < 16; d++) s += sow[c][d] * yup[d];
        size_t o = (((size_t)(b * 64 + c)) << 14) + pix;
        zout[o] = x[o] + s;
    }
}

// ============================================================================
// K4a: partial BN stats, 1024 blocks (16 slices x 64 channels), atomic merge.
// ============================================================================
__global__ __launch_bounds__(256) void k_bnpart(const float* __restrict__ z)
{
    __shared__ float ss[256], ss2[256];
    int c = blockIdx.x >> 4, s = blockIdx.x & 15;
    int tid = threadIdx.x;
    float sum = 0.f, sum2 = 0.f;
#pragma unroll
    for (int b = 0; b < 4; b++) {
        const float4* p = (const float4*)(z + (((size_t)(b * 64 + c)) << 14)) + s * 256;
        float4 v = p[tid];
        sum  += v.x + v.y + v.z + v.w;
        sum2 += v.x * v.x + v.y * v.y + v.z * v.z + v.w * v.w;
    }
    ss[tid] = sum; ss2[tid] = sum2;
    __syncthreads();
    for (int off = 128; off; off >>= 1) {
        if (tid < off) { ss[tid] += ss[tid + off]; ss2[tid] += ss2[tid + off]; }
        __syncthreads();
    }
    if (tid == 0) {
        atomicAdd(&g_sum[c],  ss[0]);
        atomicAdd(&g_sum2[c], ss2[0]);
    }
}

// K4b: normalize in place; scale/shift derived per block.
__global__ __launch_bounds__(256) void k_bnapply(
    float4* __restrict__ z,
    const float* __restrict__ gamma, const float* __restrict__ beta)
{
    int blk = blockIdx.x;               // 1024 blocks, quarter-plane each
    int c = (blk >> 2) & 63;
    const float inv = 1.0f / 65536.0f;
    float mean = g_sum[c] * inv;
    float var  = g_sum2[c] * inv - mean * mean;
    float sc = gamma[c] * rsqrtf(var + 1e-5f);
    float sh = beta[c] - mean * sc;
    int base = blk * 1024 + threadIdx.x;
#pragma unroll
    for (int k = 0; k < 4; k++) {
        float4 v = z[base + k * 256];
        v.x = v.x * sc + sh; v.y = v.y * sc + sh;
        v.z = v.z * sc + sh; v.w = v.w * sc + sh;
        z[base + k * 256] = v;
    }
}

// ============================================================================
extern "C" void kernel_launch(void* const* d_in, const int* in_sizes, int n_in,
                              void* d_out, int out_size)
{
    const float* x   = (const float*)d_in[0];
    const float* gw  = (const float*)d_in[1];
    const float* gb  = (const float*)d_in[2];
    const float* tw  = (const float*)d_in[3];
    const float* tb  = (const float*)d_in[4];
    const float* pw  = (const float*)d_in[5];
    const float* pb  = (const float*)d_in[6];
    const float* ow  = (const float*)d_in[7];
    const float* ob  = (const float*)d_in[8];
    const float* gam = (const float*)d_in[9];
    const float* bet = (const float*)d_in[10];
    float* out = (float*)d_out;

    k_down_proj<<<dim3(16, 4), 256>>>(x, gw, gb, tw, tb, pw, pb);
    k_attn     <<<dim3(64, 4), 256, 32768>>>();
    k_up_out   <<<dim3(64, 4), 256>>>(x, ow, ob, out);
    k_bnpart   <<<1024, 256>>>(out);
    k_bnapply  <<<1024, 256>>>((float4*)out, gam, bet);
}

// round 4
// speedup vs baseline: 1.2267x; 1.0431x over previous
#include <cuda_runtime.h>

#define LOG2E 1.4426950408889634f
#define C2OFF (20.0f * LOG2E)

typedef unsigned long long u64;

// ---------------- scratch (static device globals; no allocation) -------------
__device__ float g_th  [4][4096][16];        // queries (pre-scaled by log2e)
__device__ float g_keyT[4][32][16][128];     // keys, transposed per 128-key tile
__device__ float g_v   [4][4096][16];        // values, natural layout
__device__ float g_y   [4][4096][16];        // attention output
__device__ float g_sum [64];
__device__ float g_sum2[64];

// ---------------- helpers ----------------------------------------------------
__device__ __forceinline__ u64 pk2(float lo, float hi) {
    u64 r; asm("mov.b64 %0,{%1,%2};" : "=l"(r) : "f"(lo), "f"(hi)); return r;
}
__device__ __forceinline__ void upk2(u64 v, float &lo, float &hi) {
    asm("mov.b64 {%0,%1},%2;" : "=f"(lo), "=f"(hi) : "l"(v));
}
__device__ __forceinline__ u64 fma2_(u64 a, u64 b, u64 c) {
    u64 d; asm("fma.rn.f32x2 %0,%1,%2,%3;" : "=l"(d) : "l"(a), "l"(b), "l"(c)); return d;
}
__device__ __forceinline__ u64 add2_(u64 a, u64 b) {
    u64 d; asm("add.rn.f32x2 %0,%1,%2;" : "=l"(d) : "l"(a), "l"(b)); return d;
}
__device__ __forceinline__ float ex2f_(float x) {
    float y; asm("ex2.approx.f32 %0,%1;" : "=f"(y) : "f"(x)); return y;
}
__device__ __forceinline__ void lds128(u64 &a, u64 &b, unsigned addr) {
    asm("ld.shared.v2.u64 {%0,%1},[%2];" : "=l"(a), "=l"(b) : "r"(addr));
}
__device__ __forceinline__ void cpa16(unsigned saddr, const void* g) {
    asm volatile("{.reg .u64 gp; cvta.to.global.u64 gp, %1;"
                 " cp.async.cg.shared.global [%0],[gp],16;}"
                 :: "r"(saddr), "l"(g));
}
__device__ __forceinline__ void cpa_commit() {
    asm volatile("cp.async.commit_group;");
}

// ============================================================================
// K1: downsample (point-sample at (2i+1,2j+1)) + g/theta/phi projections.
// K written TRANSPOSED per 128-key tile; V natural. Zeroes BN accumulators.
// ============================================================================
__global__ __launch_bounds__(256) void k_down_proj(
    const float* __restrict__ x,
    const float* __restrict__ gw, const float* __restrict__ gb,
    const float* __restrict__ tw, const float* __restrict__ tb,
    const float* __restrict__ pw, const float* __restrict__ pb)
{
    __shared__ float sw[48][64];   // [0:16)=g, [16:32)=theta*log2e, [32:48)=phi
    __shared__ float sb[48];
    int tid = threadIdx.x;
    if (blockIdx.x == 0 && blockIdx.y == 0 && tid < 128) {
        if (tid < 64) g_sum[tid] = 0.f; else g_sum2[tid - 64] = 0.f;
    }
    for (int idx = tid; idx < 1024; idx += 256) {
        int o = idx >> 6, c = idx & 63;
        sw[o][c]      = gw[idx];
        sw[16 + o][c] = tw[idx] * LOG2E;
        sw[32 + o][c] = pw[idx];
    }
    if (tid < 16) { sb[tid] = gb[tid]; sb[16 + tid] = tb[tid] * LOG2E; sb[32 + tid] = pb[tid]; }
    __syncthreads();

    int b = blockIdx.y;
    int n = blockIdx.x * 256 + tid;           // 0..4095
    int i = n >> 6, j = n & 63;
    const float* xp = x + (((size_t)b * 64) << 14) + (2 * i + 1) * 128 + (2 * j + 1);

    float acc[48];
#pragma unroll
    for (int o = 0; o < 48; o++) acc[o] = sb[o];

    for (int c = 0; c < 64; c++) {
        float v = xp[(size_t)c << 14];
#pragma unroll
        for (int o = 0; o < 48; o++) acc[o] += sw[o][c] * v;
    }

    float* pt = &g_th[b][n][0];
    float* pv = &g_v [b][n][0];
    int tile = n >> 7, jj = n & 127;
#pragma unroll
    for (int o = 0; o < 16; o++) {
        pv[o] = acc[o];
        pt[o] = acc[16 + o];
        g_keyT[b][tile][o][jj] = acc[32 + o];   // coalesced per fixed o
    }
}

// ============================================================================
// K2: attention, N=4096, D=16, max-free softmax (fixed offset 20, exp2 domain).
// grid (64 qtiles, 4 batches) = 256 CTAs, 256 threads, 32KB smem -> 2 CTAs/SM.
//   qg = tid&31 -> 2 queries; warp id = key split (8 splits of 512 keys).
// Duplicated-query f32x2 pairs hoisted out of all loops (64 persistent regs).
// ============================================================================
#define TK 128
#define NT 32
extern __shared__ u64 dynsm[];   // 32768B: K0 |8K| K1 |8K| V0 |8K| V1 |8K|

__global__ __launch_bounds__(256, 2) void k_attn()
{
    int tid = threadIdx.x;
    int qg  = tid & 31;
    int sp  = tid >> 5;            // warp id == key split
    int b   = blockIdx.y;
    int qbase = blockIdx.x * 64;

    unsigned sbase = (unsigned)__cvta_generic_to_shared(dynsm);

    // load 2 queries, duplicate each dim into both f32x2 lanes ONCE (hoisted)
    const float4* thp = (const float4*)&g_th[b][qbase + 2 * qg][0];
    u64 q0d[16], q1d[16];
#pragma unroll
    for (int r = 0; r < 4; r++) {
        float4 v0 = thp[r], v1 = thp[4 + r];
        q0d[r * 4 + 0] = pk2(v0.x, v0.x); q0d[r * 4 + 1] = pk2(v0.y, v0.y);
        q0d[r * 4 + 2] = pk2(v0.z, v0.z); q0d[r * 4 + 3] = pk2(v0.w, v0.w);
        q1d[r * 4 + 0] = pk2(v1.x, v1.x); q1d[r * 4 + 1] = pk2(v1.y, v1.y);
        q1d[r * 4 + 2] = pk2(v1.z, v1.z); q1d[r * 4 + 3] = pk2(v1.w, v1.w);
    }

    u64 a0[8], a1[8];
#pragma unroll
    for (int d = 0; d < 8; d++) { a0[d] = 0ULL; a1[d] = 0ULL; }
    float la = 0.f, lb = 0.f;
    const u64 negc2 = pk2(-C2OFF, -C2OFF);

    const float* Kg = &g_keyT[b][0][0][0];   // 32 tiles * 2048 floats
    const float* Vg = &g_v   [b][0][0];

    // prefetch tile 0
#pragma unroll
    for (int k = 0; k < 2; k++) {
        int ch = tid + k * 256;              // 512 chunks of 16B per array
        cpa16(sbase + ch * 16,         Kg + ch * 4);
        cpa16(sbase + 16384 + ch * 16, Vg + ch * 4);
    }
    cpa_commit();

    for (int t = 0; t < NT; t++) {
        if (t + 1 < NT) {
            int nb = (t + 1) & 1;
            const float* ks = Kg + (t + 1) * 2048;
            const float* vs = Vg + (t + 1) * 2048;
#pragma unroll
            for (int k = 0; k < 2; k++) {
                int ch = tid + k * 256;
                cpa16(sbase + nb * 8192 + ch * 16,         ks + ch * 4);
                cpa16(sbase + 16384 + nb * 8192 + ch * 16, vs + ch * 4);
            }
            cpa_commit();
            asm volatile("cp.async.wait_group 1;");
        } else {
            asm volatile("cp.async.wait_group 0;");
        }
        __syncthreads();

        unsigned skb = sbase + (t & 1) * 8192;           // K: [d][j] floats
        unsigned svb = sbase + 16384 + (t & 1) * 8192;   // V: [j][d] floats

#pragma unroll 1
        for (int ii = 0; ii < 4; ii++) {
            int j0 = ii * 32 + sp * 4;       // this thread's 4 keys
            unsigned ka = skb + j0 * 4;
            u64 sA0 = negc2, sA1 = negc2, sB0 = negc2, sB1 = negc2;
#pragma unroll
            for (int d = 0; d < 16; d++) {
                u64 k01, k23; lds128(k01, k23, ka + d * 512);
                sA0 = fma2_(q0d[d], k01, sA0); sA1 = fma2_(q0d[d], k23, sA1);
                sB0 = fma2_(q1d[d], k01, sB0); sB1 = fma2_(q1d[d], k23, sB1);
            }
            float pa[4], pb[4], e0, e1;
            upk2(sA0, e0, e1); pa[0] = ex2f_(e0); pa[1] = ex2f_(e1);
            upk2(sA1, e0, e1); pa[2] = ex2f_(e0); pa[3] = ex2f_(e1);
            upk2(sB0, e0, e1); pb[0] = ex2f_(e0); pb[1] = ex2f_(e1);
            upk2(sB1, e0, e1); pb[2] = ex2f_(e0); pb[3] = ex2f_(e1);
            la += (pa[0] + pa[1]) + (pa[2] + pa[3]);
            lb += (pb[0] + pb[1]) + (pb[2] + pb[3]);
#pragma unroll
            for (int jj = 0; jj < 4; jj++) {
                u64 pda = pk2(pa[jj], pa[jj]);
                u64 pdb = pk2(pb[jj], pb[jj]);
                unsigned va = svb + (j0 + jj) * 64;
#pragma unroll
                for (int dpp = 0; dpp < 4; dpp++) {
                    u64 v01, v23; lds128(v01, v23, va + dpp * 16);
                    a0[2 * dpp]     = fma2_(pda, v01, a0[2 * dpp]);
                    a0[2 * dpp + 1] = fma2_(pda, v23, a0[2 * dpp + 1]);
                    a1[2 * dpp]     = fma2_(pdb, v01, a1[2 * dpp]);
                    a1[2 * dpp + 1] = fma2_(pdb, v23, a1[2 * dpp + 1]);
                }
            }
        }
        __syncthreads();
    }

    // ---- merge 8 key-splits (aliases tile smem; deterministic order) --------
    u64 (*marr)[2][8] = (u64 (*)[2][8])dynsm;          // 4096B
    float* larr = (float*)(dynsm + 512);               // 256B
    for (int s = 0; s < 8; s++) {
        if (sp == s) {
            if (s == 0) {
#pragma unroll
                for (int d = 0; d < 8; d++) { marr[qg][0][d] = a0[d]; marr[qg][1][d] = a1[d]; }
                larr[qg * 2] = la; larr[qg * 2 + 1] = lb;
            } else {
#pragma unroll
                for (int d = 0; d < 8; d++) {
                    marr[qg][0][d] = add2_(marr[qg][0][d], a0[d]);
                    marr[qg][1][d] = add2_(marr[qg][1][d], a1[d]);
                }
                larr[qg * 2]     += la;
                larr[qg * 2 + 1] += lb;
            }
        }
        __syncthreads();
    }

    // ---- normalize + write y: 32 qg * 2 q * 8 dpairs = 512 pairs ------------
    for (int it = tid; it < 512; it += 256) {
        int qg2 = it >> 4, q = (it >> 3) & 1, dp = it & 7;
        u64 av = marr[qg2][q][dp];
        float l = larr[qg2 * 2 + q];
        float ax, ay; upk2(av, ax, ay);
        float inv = __fdividef(1.f, l);
        int qi = qbase + qg2 * 2 + q;
        g_y[b][qi][2 * dp]     = ax * inv;
        g_y[b][qi][2 * dp + 1] = ay * inv;
    }
}

// ============================================================================
// K3: upsample 2x + out projection (16->64, channel-pair f32x2) + residual.
// ============================================================================
__global__ __launch_bounds__(256) void k_up_out(
    const float* __restrict__ x,
    const float* __restrict__ ow, const float* __restrict__ ob,
    float* __restrict__ zout)
{
    __shared__ u64 sw2[32][16];   // [cpair][d] = (ow[2cp][d], ow[2cp+1][d])
    __shared__ u64 sb2[32];
    int tid = threadIdx.x;
    for (int idx = tid; idx < 512; idx += 256) {
        int cp = idx >> 4, d = idx & 15;
        sw2[cp][d] = pk2(ow[(2 * cp) * 16 + d], ow[(2 * cp + 1) * 16 + d]);
    }
    if (tid < 32) sb2[tid] = pk2(ob[2 * tid], ob[2 * tid + 1]);
    __syncthreads();

    int b = blockIdx.y;
    int pix = blockIdx.x * 256 + tid;   // 0..16383
    int i = pix >> 7, j = pix & 127;

    int r0 = (i - 1) >> 1; if (r0 < 0) r0 = 0;
    int r1 = i >> 1;
    int c0 = (j - 1) >> 1; if (c0 < 0) c0 = 0;
    int c1 = j >> 1;

    const float* yb = &g_y[b][0][0];
    const float4* t00 = (const float4*)(yb + (r0 * 64 + c0) * 16);
    const float4* t01 = (const float4*)(yb + (r0 * 64 + c1) * 16);
    const float4* t10 = (const float4*)(yb + (r1 * 64 + c0) * 16);
    const float4* t11 = (const float4*)(yb + (r1 * 64 + c1) * 16);

    u64 yd[16];   // upsampled value duplicated into both lanes
#pragma unroll
    for (int r = 0; r < 4; r++) {
        float4 a = t00[r], bb = t01[r], c = t10[r], d = t11[r];
        float y0 = 0.25f * (a.x + bb.x + c.x + d.x);
        float y1 = 0.25f * (a.y + bb.y + c.y + d.y);
        float y2 = 0.25f * (a.z + bb.z + c.z + d.z);
        float y3 = 0.25f * (a.w + bb.w + c.w + d.w);
        yd[r * 4 + 0] = pk2(y0, y0); yd[r * 4 + 1] = pk2(y1, y1);
        yd[r * 4 + 2] = pk2(y2, y2); yd[r * 4 + 3] = pk2(y3, y3);
    }

    size_t base = (((size_t)b * 64) << 14) + pix;
#pragma unroll 4
    for (int cp = 0; cp < 32; cp++) {
        u64 acc = sb2[cp];
#pragma unroll
        for (int d = 0; d < 16; d++) acc = fma2_(yd[d], sw2[cp][d], acc);
        float s0, s1; upk2(acc, s0, s1);
        size_t o0 = base + (((size_t)(2 * cp))     << 14);
        size_t o1 = base + (((size_t)(2 * cp + 1)) << 14);
        zout[o0] = x[o0] + s0;
        zout[o1] = x[o1] + s1;
    }
}

// ============================================================================
// K4a: partial BN stats, 512 blocks (8 slices x 64 channels),
//      warp-shuffle reduce + one atomicAdd per warp. No smem, no sync tree.
// ============================================================================
__global__ __launch_bounds__(256) void k_bnpart(const float* __restrict__ z)
{
    int c = blockIdx.x >> 3, s = blockIdx.x & 7;
    int tid = threadIdx.x;
    float sum = 0.f, sum2 = 0.f;
#pragma unroll
    for (int b = 0; b < 4; b++) {
        const float4* p = (const float4*)(z + (((size_t)(b * 64 + c)) << 14)) + s * 512;
#pragma unroll
        for (int k = 0; k < 2; k++) {
            float4 v = p[tid + k * 256];
            sum  += v.x + v.y + v.z + v.w;
            sum2 += v.x * v.x + v.y * v.y + v.z * v.z + v.w * v.w;
        }
    }
#pragma unroll
    for (int off = 16; off; off >>= 1) {
        sum  += __shfl_xor_sync(0xffffffffu, sum,  off);
        sum2 += __shfl_xor_sync(0xffffffffu, sum2, off);
    }
    if ((tid & 31) == 0) {
        atomicAdd(&g_sum[c],  sum);
        atomicAdd(&g_sum2[c], sum2);
    }
}

// K4b: normalize in place; scale/shift derived per block.
__global__ __launch_bounds__(256) void k_bnapply(
    float4* __restrict__ z,
    const float* __restrict__ gamma, const float* __restrict__ beta)
{
    int blk = blockIdx.x;               // 1024 blocks, quarter-plane each
    int c = (blk >> 2) & 63;
    const float inv = 1.0f / 65536.0f;
    float mean = g_sum[c] * inv;
    float var  = g_sum2[c] * inv - mean * mean;
    float sc = gamma[c] * rsqrtf(var + 1e-5f);
    float sh = beta[c] - mean * sc;
    int base = blk * 1024 + threadIdx.x;
#pragma unroll
    for (int k = 0; k < 4; k++) {
        float4 v = z[base + k * 256];
        v.x = v.x * sc + sh; v.y = v.y * sc + sh;
        v.z = v.z * sc + sh; v.w = v.w * sc + sh;
        z[base + k * 256] = v;
    }
}

// ============================================================================
extern "C" void kernel_launch(void* const* d_in, const int* in_sizes, int n_in,
                              void* d_out, int out_size)
{
    const float* x   = (const float*)d_in[0];
    const float* gw  = (const float*)d_in[1];
    const float* gb  = (const float*)d_in[2];
    const float* tw  = (const float*)d_in[3];
    const float* tb  = (const float*)d_in[4];
    const float* pw  = (const float*)d_in[5];
    const float* pb  = (const float*)d_in[6];
    const float* ow  = (const float*)d_in[7];
    const float* ob  = (const float*)d_in[8];
    const float* gam = (const float*)d_in[9];
    const float* bet = (const float*)d_in[10];
    float* out = (float*)d_out;

    k_down_proj<<<dim3(16, 4), 256>>>(x, gw, gb, tw, tb, pw, pb);
    k_attn     <<<dim3(64, 4), 256, 32768>>>();
    k_up_out   <<<dim3(64, 4), 256>>>(x, ow, ob, out);
    k_bnpart   <<<512, 256>>>(out);
    k_bnapply  <<<1024, 256>>>((float4*)out, gam, bet);
}

// round 6
// speedup vs baseline: 1.8756x; 1.5289x over previous
#include <cuda_runtime.h>

#define LOG2E 1.4426950408889634f
#define C2OFF (20.0f * LOG2E)

typedef unsigned long long u64;
typedef unsigned int u32;
typedef unsigned short u16;

// ---------------- scratch (static device globals; no allocation) -------------
// Tile image (17920B): Khi[128][36B] | Klo[128][36B] | Vthi[16][272B] | Vtlo[16][272B]
#define IMG_KLO 4608
#define IMG_VH  9216
#define IMG_VL  13568
#define IMG_B   17920
__device__ u32   g_img[4][32][IMG_B / 4];
__device__ float g_th  [4][4096][16];     // queries (pre-scaled by log2e)
__device__ float g_y   [4][4096][16];     // attention output
__device__ float g_sum [64];
__device__ float g_sum2[64];

// ---------------- helpers ----------------------------------------------------
__device__ __forceinline__ u64 pk2(float lo, float hi) {
    u64 r; asm("mov.b64 %0,{%1,%2};" : "=l"(r) : "f"(lo), "f"(hi)); return r;
}
__device__ __forceinline__ void upk2(u64 v, float &lo, float &hi) {
    asm("mov.b64 {%0,%1},%2;" : "=f"(lo), "=f"(hi) : "l"(v));
}
__device__ __forceinline__ u64 fma2_(u64 a, u64 b, u64 c) {
    u64 d; asm("fma.rn.f32x2 %0,%1,%2,%3;" : "=l"(d) : "l"(a), "l"(b), "l"(c)); return d;
}
__device__ __forceinline__ float ex2f_(float x) {
    float y; asm("ex2.approx.f32 %0,%1;" : "=f"(y) : "f"(x)); return y;
}
// pack: low 16 = bf16(lo), high 16 = bf16(hi)
__device__ __forceinline__ u32 pkbf(float lo, float hi) {
    u32 r; asm("cvt.rn.bf16x2.f32 %0,%1,%2;" : "=r"(r) : "f"(hi), "f"(lo)); return r;
}
__device__ __forceinline__ float lo_f(u32 p) { return __uint_as_float(p << 16); }
__device__ __forceinline__ float hi_f(u32 p) { return __uint_as_float(p & 0xffff0000u); }

__device__ __forceinline__ u32 lds32(u32 a) {
    u32 v; asm("ld.shared.b32 %0,[%1];" : "=r"(v) : "r"(a)); return v;
}
__device__ __forceinline__ void cpa16(unsigned saddr, const void* g) {
    asm volatile("{.reg .u64 gp; cvta.to.global.u64 gp, %1;"
                 " cp.async.cg.shared.global [%0],[gp],16;}"
                 :: "r"(saddr), "l"(g));
}
__device__ __forceinline__ void cpa_commit() { asm volatile("cp.async.commit_group;"); }
__device__ __forceinline__ u32 smem_u32(const void* p) {
    u32 a; asm("{ .reg .u64 t; cvta.to.shared.u64 t, %1; cvt.u32.u64 %0, t; }" : "=r"(a) : "l"(p));
    return a;
}

// D += A * B  (m16n8k16, bf16 in, fp32 accum)
#define MMA16816(d, a, b) \
    asm("mma.sync.aligned.m16n8k16.row.col.f32.bf16.bf16.f32 " \
        "{%0,%1,%2,%3},{%4,%5,%6,%7},{%8,%9},{%0,%1,%2,%3};" \
        : "+f"((d)[0]), "+f"((d)[1]), "+f"((d)[2]), "+f"((d)[3]) \
        : "r"((a)[0]), "r"((a)[1]), "r"((a)[2]), "r"((a)[3]), "r"((b)[0]), "r"((b)[1]))

// ============================================================================
// K1: downsample (point-sample at (2i+1,2j+1)) + g/theta/phi projections.
// theta -> g_th fp32 (log2e-scaled). phi/g -> bf16 hi/lo tile images.
// ============================================================================
__global__ __launch_bounds__(256) void k_down_proj(
    const float* __restrict__ x,
    const float* __restrict__ gw, const float* __restrict__ gb,
    const float* __restrict__ tw, const float* __restrict__ tb,
    const float* __restrict__ pw, const float* __restrict__ pb)
{
    __shared__ float sw[48][64];
    __shared__ float sb[48];
    int tid = threadIdx.x;
    if (blockIdx.x == 0 && blockIdx.y == 0 && tid < 128) {
        if (tid < 64) g_sum[tid] = 0.f; else g_sum2[tid - 64] = 0.f;
    }
    for (int idx = tid; idx < 1024; idx += 256) {
        int o = idx >> 6, c = idx & 63;
        sw[o][c]      = gw[idx];
        sw[16 + o][c] = tw[idx] * LOG2E;
        sw[32 + o][c] = pw[idx];
    }
    if (tid < 16) { sb[tid] = gb[tid]; sb[16 + tid] = tb[tid] * LOG2E; sb[32 + tid] = pb[tid]; }
    __syncthreads();

    int b = blockIdx.y;
    int n = blockIdx.x * 256 + tid;           // 0..4095
    int i = n >> 6, j = n & 63;
    const float* xp = x + (((size_t)b * 64) << 14) + (2 * i + 1) * 128 + (2 * j + 1);

    float acc[48];
#pragma unroll
    for (int o = 0; o < 48; o++) acc[o] = sb[o];
    for (int c = 0; c < 64; c++) {
        float v = xp[(size_t)c << 14];
#pragma unroll
        for (int o = 0; o < 48; o++) acc[o] += sw[o][c] * v;
    }

    int tile = n >> 7, jj = n & 127;
    float* pt = &g_th[b][n][0];
#pragma unroll
    for (int o = 0; o < 16; o++) pt[o] = acc[16 + o];

    char* img = (char*)&g_img[b][tile][0];
    // K rows (36B): d-pairs packed (low = even d)
#pragma unroll
    for (int cc = 0; cc < 8; cc++) {
        float v0 = acc[32 + 2 * cc], v1 = acc[32 + 2 * cc + 1];
        u32 h = pkbf(v0, v1);
        u32 l = pkbf(v0 - lo_f(h), v1 - hi_f(h));
        *(u32*)(img + jj * 36 + cc * 4)           = h;
        *(u32*)(img + IMG_KLO + jj * 36 + cc * 4) = l;
    }
    // V^T rows (272B): row d, col jj
#pragma unroll
    for (int d = 0; d < 16; d++) {
        float a = acc[d];
        u32 h = pkbf(a, 0.f);
        u32 l = pkbf(a - lo_f(h), 0.f);
        *(u16*)(img + IMG_VH + d * 272 + jj * 2) = (u16)h;
        *(u16*)(img + IMG_VL + d * 272 + jj * 2) = (u16)l;
    }
}

// ============================================================================
// K2: mma.sync flash attention. grid (32 qtiles, 4 batches), 256 thr (8 warps).
// Warp w: 16 queries. bf16 hi/lo splits, 3 MMAs/product. Max-free exp2 softmax
// (offset folded into accumulator init). P repacked D-frag -> A-frag in regs.
// ============================================================================
extern __shared__ u64 dynsm[];   // 2 x 17920B tile buffers

__global__ __launch_bounds__(256, 1) void k_attn_mma()
{
    int tid = threadIdx.x, w = tid >> 5, ln = tid & 31;
    int gr = ln >> 2, tc = ln & 3;
    int b = blockIdx.y, qbase = blockIdx.x * 128;
    u32 sbm = smem_u32(dynsm);

    // ---- Q A-fragments (persistent) ----------------------------------------
    const float2* q0p = (const float2*)&g_th[b][qbase + w * 16 + gr][0];
    const float2* q1p = (const float2*)&g_th[b][qbase + w * 16 + gr + 8][0];
    float2 x0 = q0p[tc], x2 = q0p[tc + 4];
    float2 x1 = q1p[tc], x3 = q1p[tc + 4];
    u32 Ah[4], Al[4];
    Ah[0] = pkbf(x0.x, x0.y); Al[0] = pkbf(x0.x - lo_f(Ah[0]), x0.y - hi_f(Ah[0]));
    Ah[1] = pkbf(x1.x, x1.y); Al[1] = pkbf(x1.x - lo_f(Ah[1]), x1.y - hi_f(Ah[1]));
    Ah[2] = pkbf(x2.x, x2.y); Al[2] = pkbf(x2.x - lo_f(Ah[2]), x2.y - hi_f(Ah[2]));
    Ah[3] = pkbf(x3.x, x3.y); Al[3] = pkbf(x3.x - lo_f(Ah[3]), x3.y - hi_f(Ah[3]));

    float y0[4] = {0.f, 0.f, 0.f, 0.f};
    float y1[4] = {0.f, 0.f, 0.f, 0.f};
    float l0 = 0.f, l1 = 0.f;

    // ---- prefetch tile 0 ----------------------------------------------------
    {
        const u32* src = &g_img[b][0][0];
        for (int ch = tid; ch < 1120; ch += 256) cpa16(sbm + ch * 16, src + ch * 4);
        cpa_commit();
    }

    for (int t = 0; t < 32; t++) {
        if (t + 1 < 32) {
            u32 nbuf = sbm + (u32)((t + 1) & 1) * IMG_B;
            const u32* src = &g_img[b][t + 1][0];
            for (int ch = tid; ch < 1120; ch += 256) cpa16(nbuf + ch * 16, src + ch * 4);
            cpa_commit();
            asm volatile("cp.async.wait_group 1;");
        } else {
            asm volatile("cp.async.wait_group 0;");
        }
        __syncthreads();

        u32 kb = sbm + (u32)(t & 1) * IMG_B;
        u32 vb = kb + IMG_VH;

#pragma unroll 2
        for (int kp = 0; kp < 8; kp++) {
            u32 pah[4], pal[4];
#pragma unroll
            for (int h = 0; h < 2; h++) {
                int nb = kp * 2 + h;
                u32 ba = kb + (u32)((nb * 8 + gr) * 36 + tc * 4);
                u32 bh[2] = { lds32(ba), lds32(ba + 16) };
                u32 bl[2] = { lds32(ba + IMG_KLO), lds32(ba + IMG_KLO + 16) };
                float d[4] = { -C2OFF, -C2OFF, -C2OFF, -C2OFF };
                MMA16816(d, Ah, bh);
                MMA16816(d, Ah, bl);
                MMA16816(d, Al, bh);
                float p0 = ex2f_(d[0]), p1 = ex2f_(d[1]);
                float p2 = ex2f_(d[2]), p3 = ex2f_(d[3]);
                l0 += p0 + p1;
                l1 += p2 + p3;
                u32 h0 = pkbf(p0, p1), h1 = pkbf(p2, p3);
                pah[0 + 2 * h] = h0;
                pah[1 + 2 * h] = h1;
                pal[0 + 2 * h] = pkbf(p0 - lo_f(h0), p1 - hi_f(h0));
                pal[1 + 2 * h] = pkbf(p2 - lo_f(h1), p3 - hi_f(h1));
            }
            // PV for these 16 keys
            {
                u32 va = vb + (u32)(gr * 272 + kp * 32 + tc * 4);
                u32 vh[2] = { lds32(va), lds32(va + 16) };
                u32 vl[2] = { lds32(va + 4352), lds32(va + 4352 + 16) };
                MMA16816(y0, pah, vh);
                MMA16816(y0, pal, vh);
                MMA16816(y0, pah, vl);
            }
            {
                u32 va = vb + (u32)((8 + gr) * 272 + kp * 32 + tc * 4);
                u32 vh[2] = { lds32(va), lds32(va + 16) };
                u32 vl[2] = { lds32(va + 4352), lds32(va + 4352 + 16) };
                MMA16816(y1, pah, vh);
                MMA16816(y1, pal, vh);
                MMA16816(y1, pah, vl);
            }
        }
        __syncthreads();
    }

    // ---- row sums across the 4-thread groups --------------------------------
    l0 += __shfl_xor_sync(0xffffffffu, l0, 1);
    l0 += __shfl_xor_sync(0xffffffffu, l0, 2);
    l1 += __shfl_xor_sync(0xffffffffu, l1, 1);
    l1 += __shfl_xor_sync(0xffffffffu, l1, 2);
    float inv0 = __fdividef(1.f, l0);
    float inv1 = __fdividef(1.f, l1);

    int r0 = qbase + w * 16 + gr;
    float2* o0 = (float2*)&g_y[b][r0][0];
    float2* o1 = (float2*)&g_y[b][r0 + 8][0];
    o0[tc]     = make_float2(y0[0] * inv0, y0[1] * inv0);
    o0[tc + 4] = make_float2(y1[0] * inv0, y1[1] * inv0);
    o1[tc]     = make_float2(y0[2] * inv1, y0[3] * inv1);
    o1[tc + 4] = make_float2(y1[2] * inv1, y1[3] * inv1);
}

// ============================================================================
// K3: upsample 2x + out projection (16->64, channel-pair f32x2) + residual.
// ============================================================================
__global__ __launch_bounds__(256) void k_up_out(
    const float* __restrict__ x,
    const float* __restrict__ ow, const float* __restrict__ ob,
    float* __restrict__ zout)
{
    __shared__ u64 sw2[32][16];
    __shared__ u64 sb2[32];
    int tid = threadIdx.x;
    for (int idx = tid; idx < 512; idx += 256) {
        int cp = idx >> 4, d = idx & 15;
        sw2[cp][d] = pk2(ow[(2 * cp) * 16 + d], ow[(2 * cp + 1) * 16 + d]);
    }
    if (tid < 32) sb2[tid] = pk2(ob[2 * tid], ob[2 * tid + 1]);
    __syncthreads();

    int b = blockIdx.y;
    int pix = blockIdx.x * 256 + tid;
    int i = pix >> 7, j = pix & 127;
    int r0 = (i - 1) >> 1; if (r0 < 0) r0 = 0;
    int r1 = i >> 1;
    int c0 = (j - 1) >> 1; if (c0 < 0) c0 = 0;
    int c1 = j >> 1;

    const float* yb = &g_y[b][0][0];
    const float4* t00 = (const float4*)(yb + (r0 * 64 + c0) * 16);
    const float4* t01 = (const float4*)(yb + (r0 * 64 + c1) * 16);
    const float4* t10 = (const float4*)(yb + (r1 * 64 + c0) * 16);
    const float4* t11 = (const float4*)(yb + (r1 * 64 + c1) * 16);

    u64 yd[16];
#pragma unroll
    for (int r = 0; r < 4; r++) {
        float4 a = t00[r], bb = t01[r], c = t10[r], d = t11[r];
        float v0 = 0.25f * (a.x + bb.x + c.x + d.x);
        float v1 = 0.25f * (a.y + bb.y + c.y + d.y);
        float v2 = 0.25f * (a.z + bb.z + c.z + d.z);
        float v3 = 0.25f * (a.w + bb.w + c.w + d.w);
        yd[r * 4 + 0] = pk2(v0, v0); yd[r * 4 + 1] = pk2(v1, v1);
        yd[r * 4 + 2] = pk2(v2, v2); yd[r * 4 + 3] = pk2(v3, v3);
    }

    size_t base = (((size_t)b * 64) << 14) + pix;
#pragma unroll 4
    for (int cp = 0; cp < 32; cp++) {
        u64 acc = sb2[cp];
#pragma unroll
        for (int d = 0; d < 16; d++) acc = fma2_(yd[d], sw2[cp][d], acc);
        float s0, s1; upk2(acc, s0, s1);
        size_t o0 = base + (((size_t)(2 * cp))     << 14);
        size_t o1 = base + (((size_t)(2 * cp + 1)) << 14);
        zout[o0] = x[o0] + s0;
        zout[o1] = x[o1] + s1;
    }
}

// ============================================================================
// K4a: partial BN stats; 1024 blocks (16 slices x 64 ch), shuffle + atomics.
// ============================================================================
__global__ __launch_bounds__(256) void k_bnpart(const float* __restrict__ z)
{
    int c = blockIdx.x >> 4, s = blockIdx.x & 15;
    int tid = threadIdx.x;
    float sum = 0.f, sum2 = 0.f;
#pragma unroll
    for (int b = 0; b < 4; b++) {
        const float4* p = (const float4*)(z + (((size_t)(b * 64 + c)) << 14)) + s * 256;
        float4 v = p[tid];
        sum  += v.x + v.y + v.z + v.w;
        sum2 += v.x * v.x + v.y * v.y + v.z * v.z + v.w * v.w;
    }
#pragma unroll
    for (int off = 16; off; off >>= 1) {
        sum  += __shfl_xor_sync(0xffffffffu, sum,  off);
        sum2 += __shfl_xor_sync(0xffffffffu, sum2, off);
    }
    if ((tid & 31) == 0) {
        atomicAdd(&g_sum[c],  sum);
        atomicAdd(&g_sum2[c], sum2);
    }
}

__global__ __launch_bounds__(256) void k_bnapply(
    float4* __restrict__ z,
    const float* __restrict__ gamma, const float* __restrict__ beta)
{
    int blk = blockIdx.x;
    int c = (blk >> 2) & 63;
    const float inv = 1.0f / 65536.0f;
    float mean = g_sum[c] * inv;
    float var  = g_sum2[c] * inv - mean * mean;
    float sc = gamma[c] * rsqrtf(var + 1e-5f);
    float sh = beta[c] - mean * sc;
    int base = blk * 1024 + threadIdx.x;
#pragma unroll
    for (int k = 0; k < 4; k++) {
        float4 v = z[base + k * 256];
        v.x = v.x * sc + sh; v.y = v.y * sc + sh;
        v.z = v.z * sc + sh; v.w = v.w * sc + sh;
        z[base + k * 256] = v;
    }
}

// ============================================================================
extern "C" void kernel_launch(void* const* d_in, const int* in_sizes, int n_in,
                              void* d_out, int out_size)
{
    const float* x   = (const float*)d_in[0];
    const float* gw  = (const float*)d_in[1];
    const float* gb  = (const float*)d_in[2];
    const float* tw  = (const float*)d_in[3];
    const float* tb  = (const float*)d_in[4];
    const float* pw  = (const float*)d_in[5];
    const float* pb  = (const float*)d_in[6];
    const float* ow  = (const float*)d_in[7];
    const float* ob  = (const float*)d_in[8];
    const float* gam = (const float*)d_in[9];
    const float* bet = (const float*)d_in[10];
    float* out = (float*)d_out;

    cudaFuncSetAttribute(k_attn_mma, cudaFuncAttributeMaxDynamicSharedMemorySize, 2 * IMG_B);

    k_down_proj<<<dim3(16, 4), 256>>>(x, gw, gb, tw, tb, pw, pb);
    k_attn_mma <<<dim3(32, 4), 256, 2 * IMG_B>>>();
    k_up_out   <<<dim3(64, 4), 256>>>(x, ow, ob, out);
    k_bnpart   <<<1024, 256>>>(out);
    k_bnapply  <<<1024, 256>>>((float4*)out, gam, bet);
}

// round 8
// speedup vs baseline: 2.0366x; 1.0858x over previous
#include <cuda_runtime.h>

#define LOG2E 1.4426950408889634f
#define C2OFF (20.0f * LOG2E)

typedef unsigned long long u64;
typedef unsigned int u32;
typedef unsigned short u16;

// ---------------- scratch (static device globals; no allocation) -------------
// Tile image (17920B): Khi[128][36B] | Klo[128][36B] | Vthi[16][272B] | Vtlo[16][272B]
#define IMG_KLO 4608
#define IMG_VH  9216
#define IMG_VL  13568
#define IMG_B   17920
__device__ u32   g_img[4][32][IMG_B / 4];
__device__ float g_th  [4][4096][16];     // queries (pre-scaled by log2e)
__device__ float g_y   [4][4096][16];     // attention output
__device__ float g_sum [64];
__device__ float g_sum2[64];

// ---------------- helpers ----------------------------------------------------
__device__ __forceinline__ u64 pk2(float lo, float hi) {
    u64 r; asm("mov.b64 %0,{%1,%2};" : "=l"(r) : "f"(lo), "f"(hi)); return r;
}
__device__ __forceinline__ void upk2(u64 v, float &lo, float &hi) {
    asm("mov.b64 {%0,%1},%2;" : "=f"(lo), "=f"(hi) : "l"(v));
}
__device__ __forceinline__ u64 fma2_(u64 a, u64 b, u64 c) {
    u64 d; asm("fma.rn.f32x2 %0,%1,%2,%3;" : "=l"(d) : "l"(a), "l"(b), "l"(c)); return d;
}
__device__ __forceinline__ float ex2f_(float x) {
    float y; asm("ex2.approx.f32 %0,%1;" : "=f"(y) : "f"(x)); return y;
}
// pack: low 16 = bf16(lo), high 16 = bf16(hi)
__device__ __forceinline__ u32 pkbf(float lo, float hi) {
    u32 r; asm("cvt.rn.bf16x2.f32 %0,%1,%2;" : "=r"(r) : "f"(hi), "f"(lo)); return r;
}
__device__ __forceinline__ float lo_f(u32 p) { return __uint_as_float(p << 16); }
__device__ __forceinline__ float hi_f(u32 p) { return __uint_as_float(p & 0xffff0000u); }

__device__ __forceinline__ u32 lds32(u32 a) {
    u32 v; asm("ld.shared.b32 %0,[%1];" : "=r"(v) : "r"(a)); return v;
}
__device__ __forceinline__ void cpa16(unsigned saddr, const void* g) {
    asm volatile("{.reg .u64 gp; cvta.to.global.u64 gp, %1;"
                 " cp.async.cg.shared.global [%0],[gp],16;}"
                 :: "r"(saddr), "l"(g));
}
__device__ __forceinline__ void cpa_commit() { asm volatile("cp.async.commit_group;"); }
__device__ __forceinline__ u32 smem_u32(const void* p) {
    u32 a; asm("{ .reg .u64 t; cvta.to.shared.u64 t, %1; cvt.u32.u64 %0, t; }" : "=r"(a) : "l"(p));
    return a;
}

// D += A * B  (m16n8k16, bf16 in, fp32 accum)
#define MMA16816(d, a, b) \
    asm("mma.sync.aligned.m16n8k16.row.col.f32.bf16.bf16.f32 " \
        "{%0,%1,%2,%3},{%4,%5,%6,%7},{%8,%9},{%0,%1,%2,%3};" \
        : "+f"((d)[0]), "+f"((d)[1]), "+f"((d)[2]), "+f"((d)[3]) \
        : "r"((a)[0]), "r"((a)[1]), "r"((a)[2]), "r"((a)[3]), "r"((b)[0]), "r"((b)[1]))

// ============================================================================
// K1: downsample (point-sample at (2i+1,2j+1)) + g/theta/phi projections.
// 128 threads, grid (32,4) = 128 CTAs for SM coverage.
// ============================================================================
__global__ __launch_bounds__(128) void k_down_proj(
    const float* __restrict__ x,
    const float* __restrict__ gw, const float* __restrict__ gb,
    const float* __restrict__ tw, const float* __restrict__ tb,
    const float* __restrict__ pw, const float* __restrict__ pb)
{
    __shared__ float sw[48][64];
    __shared__ float sb[48];
    int tid = threadIdx.x;
    if (blockIdx.x == 0 && blockIdx.y == 0 && tid < 128) {
        if (tid < 64) g_sum[tid] = 0.f; else g_sum2[tid - 64] = 0.f;
    }
    for (int idx = tid; idx < 1024; idx += 128) {
        int o = idx >> 6, c = idx & 63;
        sw[o][c]      = gw[idx];
        sw[16 + o][c] = tw[idx] * LOG2E;
        sw[32 + o][c] = pw[idx];
    }
    if (tid < 16) { sb[tid] = gb[tid]; sb[16 + tid] = tb[tid] * LOG2E; sb[32 + tid] = pb[tid]; }
    __syncthreads();

    int b = blockIdx.y;
    int n = blockIdx.x * 128 + tid;           // 0..4095
    int i = n >> 6, j = n & 63;
    const float* xp = x + (((size_t)b * 64) << 14) + (2 * i + 1) * 128 + (2 * j + 1);

    float acc[48];
#pragma unroll
    for (int o = 0; o < 48; o++) acc[o] = sb[o];
    for (int c = 0; c < 64; c++) {
        float v = xp[(size_t)c << 14];
#pragma unroll
        for (int o = 0; o < 48; o++) acc[o] += sw[o][c] * v;
    }

    int tile = n >> 7, jj = n & 127;
    float* pt = &g_th[b][n][0];
#pragma unroll
    for (int o = 0; o < 16; o++) pt[o] = acc[16 + o];

    char* img = (char*)&g_img[b][tile][0];
    // K rows (36B): d-pairs packed (low = even d)
#pragma unroll
    for (int cc = 0; cc < 8; cc++) {
        float v0 = acc[32 + 2 * cc], v1 = acc[32 + 2 * cc + 1];
        u32 h = pkbf(v0, v1);
        u32 l = pkbf(v0 - lo_f(h), v1 - hi_f(h));
        *(u32*)(img + jj * 36 + cc * 4)           = h;
        *(u32*)(img + IMG_KLO + jj * 36 + cc * 4) = l;
    }
    // V^T rows (272B): row d, col jj
#pragma unroll
    for (int d = 0; d < 16; d++) {
        float a = acc[d];
        u32 h = pkbf(a, 0.f);
        u32 l = pkbf(a - lo_f(h), 0.f);
        *(u16*)(img + IMG_VH + d * 272 + jj * 2) = (u16)h;
        *(u16*)(img + IMG_VL + d * 272 + jj * 2) = (u16)l;
    }
}

// ============================================================================
// K2: mma.sync flash attention. grid (32 qtiles, 4 batches), 256 thr (8 warps).
// Warp w: 16 queries. bf16 hi/lo splits, 3 MMAs/product. Max-free exp2 softmax
// (offset folded into accumulator init). P repacked D-frag -> A-frag in regs.
// ============================================================================
extern __shared__ u64 dynsm[];   // 2 x 17920B tile buffers

__global__ __launch_bounds__(256, 1) void k_attn_mma()
{
    int tid = threadIdx.x, w = tid >> 5, ln = tid & 31;
    int gr = ln >> 2, tc = ln & 3;
    int b = blockIdx.y, qbase = blockIdx.x * 128;
    u32 sbm = smem_u32(dynsm);

    // ---- Q A-fragments (persistent) ----------------------------------------
    const float2* q0p = (const float2*)&g_th[b][qbase + w * 16 + gr][0];
    const float2* q1p = (const float2*)&g_th[b][qbase + w * 16 + gr + 8][0];
    float2 x0 = q0p[tc], x2 = q0p[tc + 4];
    float2 x1 = q1p[tc], x3 = q1p[tc + 4];
    u32 Ah[4], Al[4];
    Ah[0] = pkbf(x0.x, x0.y); Al[0] = pkbf(x0.x - lo_f(Ah[0]), x0.y - hi_f(Ah[0]));
    Ah[1] = pkbf(x1.x, x1.y); Al[1] = pkbf(x1.x - lo_f(Ah[1]), x1.y - hi_f(Ah[1]));
    Ah[2] = pkbf(x2.x, x2.y); Al[2] = pkbf(x2.x - lo_f(Ah[2]), x2.y - hi_f(Ah[2]));
    Ah[3] = pkbf(x3.x, x3.y); Al[3] = pkbf(x3.x - lo_f(Ah[3]), x3.y - hi_f(Ah[3]));

    float y0[4] = {0.f, 0.f, 0.f, 0.f};
    float y1[4] = {0.f, 0.f, 0.f, 0.f};
    float l0 = 0.f, l1 = 0.f;

    // ---- prefetch tile 0 ----------------------------------------------------
    {
        const u32* src = &g_img[b][0][0];
        for (int ch = tid; ch < 1120; ch += 256) cpa16(sbm + ch * 16, src + ch * 4);
        cpa_commit();
    }

    for (int t = 0; t < 32; t++) {
        if (t + 1 < 32) {
            u32 nbuf = sbm + (u32)((t + 1) & 1) * IMG_B;
            const u32* src = &g_img[b][t + 1][0];
            for (int ch = tid; ch < 1120; ch += 256) cpa16(nbuf + ch * 16, src + ch * 4);
            cpa_commit();
            asm volatile("cp.async.wait_group 1;");
        } else {
            asm volatile("cp.async.wait_group 0;");
        }
        __syncthreads();

        u32 kb = sbm + (u32)(t & 1) * IMG_B;
        u32 vb = kb + IMG_VH;

#pragma unroll 2
        for (int kp = 0; kp < 8; kp++) {
            u32 pah[4], pal[4];
#pragma unroll
            for (int h = 0; h < 2; h++) {
                int nb = kp * 2 + h;
                u32 ba = kb + (u32)((nb * 8 + gr) * 36 + tc * 4);
                u32 bh[2] = { lds32(ba), lds32(ba + 16) };
                u32 bl[2] = { lds32(ba + IMG_KLO), lds32(ba + IMG_KLO + 16) };
                float d[4] = { -C2OFF, -C2OFF, -C2OFF, -C2OFF };
                MMA16816(d, Ah, bh);
                MMA16816(d, Ah, bl);
                MMA16816(d, Al, bh);
                float p0 = ex2f_(d[0]), p1 = ex2f_(d[1]);
                float p2 = ex2f_(d[2]), p3 = ex2f_(d[3]);
                l0 += p0 + p1;
                l1 += p2 + p3;
                u32 h0 = pkbf(p0, p1), h1 = pkbf(p2, p3);
                pah[0 + 2 * h] = h0;
                pah[1 + 2 * h] = h1;
                pal[0 + 2 * h] = pkbf(p0 - lo_f(h0), p1 - hi_f(h0));
                pal[1 + 2 * h] = pkbf(p2 - lo_f(h1), p3 - hi_f(h1));
            }
            // PV for these 16 keys
            {
                u32 va = vb + (u32)(gr * 272 + kp * 32 + tc * 4);
                u32 vh[2] = { lds32(va), lds32(va + 16) };
                u32 vl[2] = { lds32(va + 4352), lds32(va + 4352 + 16) };
                MMA16816(y0, pah, vh);
                MMA16816(y0, pal, vh);
                MMA16816(y0, pah, vl);
            }
            {
                u32 va = vb + (u32)((8 + gr) * 272 + kp * 32 + tc * 4);
                u32 vh[2] = { lds32(va), lds32(va + 16) };
                u32 vl[2] = { lds32(va + 4352), lds32(va + 4352 + 16) };
                MMA16816(y1, pah, vh);
                MMA16816(y1, pal, vh);
                MMA16816(y1, pah, vl);
            }
        }
        __syncthreads();
    }

    // ---- row sums across the 4-thread groups --------------------------------
    l0 += __shfl_xor_sync(0xffffffffu, l0, 1);
    l0 += __shfl_xor_sync(0xffffffffu, l0, 2);
    l1 += __shfl_xor_sync(0xffffffffu, l1, 1);
    l1 += __shfl_xor_sync(0xffffffffu, l1, 2);
    float inv0 = __fdividef(1.f, l0);
    float inv1 = __fdividef(1.f, l1);

    int r0 = qbase + w * 16 + gr;
    float2* o0 = (float2*)&g_y[b][r0][0];
    float2* o1 = (float2*)&g_y[b][r0 + 8][0];
    o0[tc]     = make_float2(y0[0] * inv0, y0[1] * inv0);
    o0[tc + 4] = make_float2(y1[0] * inv0, y1[1] * inv0);
    o1[tc]     = make_float2(y0[2] * inv1, y0[3] * inv1);
    o1[tc + 4] = make_float2(y1[2] * inv1, y1[3] * inv1);
}

// ============================================================================
// K3: upsample 2x + out projection (16->64, channel-pair f32x2) + residual.
// ============================================================================
__global__ __launch_bounds__(256) void k_up_out(
    const float* __restrict__ x,
    const float* __restrict__ ow, const float* __restrict__ ob,
    float* __restrict__ zout)
{
    __shared__ u64 sw2[32][16];
    __shared__ u64 sb2[32];
    int tid = threadIdx.x;
    for (int idx = tid; idx < 512; idx += 256) {
        int cp = idx >> 4, d = idx & 15;
        sw2[cp][d] = pk2(ow[(2 * cp) * 16 + d], ow[(2 * cp + 1) * 16 + d]);
    }
    if (tid < 32) sb2[tid] = pk2(ob[2 * tid], ob[2 * tid + 1]);
    __syncthreads();

    int b = blockIdx.y;
    int pix = blockIdx.x * 256 + tid;
    int i = pix >> 7, j = pix & 127;
    int r0 = (i - 1) >> 1; if (r0 < 0) r0 = 0;
    int r1 = i >> 1;
    int c0 = (j - 1) >> 1; if (c0 < 0) c0 = 0;
    int c1 = j >> 1;

    const float* yb = &g_y[b][0][0];
    const float4* t00 = (const float4*)(yb + (r0 * 64 + c0) * 16);
    const float4* t01 = (const float4*)(yb + (r0 * 64 + c1) * 16);
    const float4* t10 = (const float4*)(yb + (r1 * 64 + c0) * 16);
    const float4* t11 = (const float4*)(yb + (r1 * 64 + c1) * 16);

    u64 yd[16];
#pragma unroll
    for (int r = 0; r < 4; r++) {
        float4 a = t00[r], bb = t01[r], c = t10[r], d = t11[r];
        float v0 = 0.25f * (a.x + bb.x + c.x + d.x);
        float v1 = 0.25f * (a.y + bb.y + c.y + d.y);
        float v2 = 0.25f * (a.z + bb.z + c.z + d.z);
        float v3 = 0.25f * (a.w + bb.w + c.w + d.w);
        yd[r * 4 + 0] = pk2(v0, v0); yd[r * 4 + 1] = pk2(v1, v1);
        yd[r * 4 + 2] = pk2(v2, v2); yd[r * 4 + 3] = pk2(v3, v3);
    }

    size_t base = (((size_t)b * 64) << 14) + pix;
#pragma unroll 4
    for (int cp = 0; cp < 32; cp++) {
        u64 acc = sb2[cp];
#pragma unroll
        for (int d = 0; d < 16; d++) acc = fma2_(yd[d], sw2[cp][d], acc);
        float s0, s1; upk2(acc, s0, s1);
        size_t o0 = base + (((size_t)(2 * cp))     << 14);
        size_t o1 = base + (((size_t)(2 * cp + 1)) << 14);
        zout[o0] = x[o0] + s0;
        zout[o1] = x[o1] + s1;
    }
}

// ============================================================================
// K4a: partial BN stats; grid 256 (64 ch x 4 slices), 16 front-batched
// float4 loads per thread (MLP=16) -> L2-latency covered.
// ============================================================================
__global__ __launch_bounds__(256) void k_bnpart(const float* __restrict__ z)
{
    int c = blockIdx.x >> 2, s = blockIdx.x & 3;
    int tid = threadIdx.x;
    float4 v[16];
#pragma unroll
    for (int b = 0; b < 4; b++) {
        const float4* p = (const float4*)(z + (((size_t)(b * 64 + c)) << 14)) + s * 1024;
#pragma unroll
        for (int k = 0; k < 4; k++)
            v[b * 4 + k] = p[k * 256 + tid];
    }
    float sum = 0.f, sum2 = 0.f;
#pragma unroll
    for (int k = 0; k < 16; k++) {
        sum  += v[k].x + v[k].y + v[k].z + v[k].w;
        sum2 += v[k].x * v[k].x + v[k].y * v[k].y + v[k].z * v[k].z + v[k].w * v[k].w;
    }
#pragma unroll
    for (int off = 16; off; off >>= 1) {
        sum  += __shfl_xor_sync(0xffffffffu, sum,  off);
        sum2 += __shfl_xor_sync(0xffffffffu, sum2, off);
    }
    if ((tid & 31) == 0) {
        atomicAdd(&g_sum[c],  sum);
        atomicAdd(&g_sum2[c], sum2);
    }
}

// K4b: normalize in place; grid 512, 8 float4 per thread (load-all/store-all).
// Each (b,c) plane = 4096 float4 = 2 blocks -> plane = blk>>1, c = plane & 63.
__global__ __launch_bounds__(256) void k_bnapply(
    float4* __restrict__ z,
    const float* __restrict__ gamma, const float* __restrict__ beta)
{
    int blk = blockIdx.x;               // 512 blocks, half-plane each
    int c = (blk >> 1) & 63;
    const float inv = 1.0f / 65536.0f;
    float mean = g_sum[c] * inv;
    float var  = g_sum2[c] * inv - mean * mean;
    float sc = gamma[c] * rsqrtf(var + 1e-5f);
    float sh = beta[c] - mean * sc;
    int base = blk * 2048 + threadIdx.x;
    float4 v[8];
#pragma unroll
    for (int k = 0; k < 8; k++) v[k] = z[base + k * 256];
#pragma unroll
    for (int k = 0; k < 8; k++) {
        v[k].x = v[k].x * sc + sh; v[k].y = v[k].y * sc + sh;
        v[k].z = v[k].z * sc + sh; v[k].w = v[k].w * sc + sh;
        z[base + k * 256] = v[k];
    }
}

// ============================================================================
extern "C" void kernel_launch(void* const* d_in, const int* in_sizes, int n_in,
                              void* d_out, int out_size)
{
    const float* x   = (const float*)d_in[0];
    const float* gw  = (const float*)d_in[1];
    const float* gb  = (const float*)d_in[2];
    const float* tw  = (const float*)d_in[3];
    const float* tb  = (const float*)d_in[4];
    const float* pw  = (const float*)d_in[5];
    const float* pb  = (const float*)d_in[6];
    const float* ow  = (const float*)d_in[7];
    const float* ob  = (const float*)d_in[8];
    const float* gam = (const float*)d_in[9];
    const float* bet = (const float*)d_in[10];
    float* out = (float*)d_out;

    cudaFuncSetAttribute(k_attn_mma, cudaFuncAttributeMaxDynamicSharedMemorySize, 2 * IMG_B);

    k_down_proj<<<dim3(32, 4), 128>>>(x, gw, gb, tw, tb, pw, pb);
    k_attn_mma <<<dim3(32, 4), 256, 2 * IMG_B>>>();
    k_up_out   <<<dim3(64, 4), 256>>>(x, ow, ob, out);
    k_bnpart   <<<256, 256>>>(out);
    k_bnapply  <<<512, 256>>>((float4*)out, gam, bet);
}